// round 5
// baseline (speedup 1.0000x reference)
#include <cuda_runtime.h>
#include <cstdint>
#include <stdint.h>
#include <math.h>

#define DEPTH 15
#define N_NODES ((1 << DEPTH) - 1)   // 32767
#define DD 512
#define HH 512
#define G4 (4 * HH)                  // 2048 gate columns, packed order [i | o | u | f]

// ---------------- scratch (device globals; allocation-free) ----------------
__device__ float g_P[(size_t)N_NODES * G4];              // x-part + bias, all gates (268 MB)
__device__ float g_Giou[(size_t)(1 << (DEPTH - 2)) * 3 * HH]; // parent-indexed iou h-part
__device__ float g_Gf[(size_t)(1 << (DEPTH - 1)) * HH];  // child-indexed f h-part
__device__ float g_h[(size_t)N_NODES * HH];
__device__ float g_c[(size_t)N_NODES * HH];
__device__ float g_Wx[(size_t)G4 * DD];                  // [i|o|u|f] x-cols (tf32-rounded)
__device__ float g_Wh[(size_t)G4 * HH];                  // [i|o|u|f] h-cols (tf32-rounded)
__device__ float g_b[G4];                                // [i|o|u|f]

// ---------------- fast activations ----------------
__device__ __forceinline__ float tanh_fast(float x) {
    float y;
    asm("tanh.approx.f32 %0, %1;" : "=f"(y) : "f"(x));
    return y;
}
__device__ __forceinline__ float sig_fast(float x) {
    return 0.5f * tanh_fast(0.5f * x) + 0.5f;
}
__device__ __forceinline__ float to_tf32(float x) {
    unsigned int r;
    asm("cvt.rna.tf32.f32 %0, %1;" : "=r"(r) : "f"(x));
    return __uint_as_float(r);
}

// ---------------- pack weights, order [i|o|u|f] ----------------
__global__ void pack_weights(const float* __restrict__ Wi, const float* __restrict__ bi,
                             const float* __restrict__ Wf, const float* __restrict__ bf,
                             const float* __restrict__ Wo, const float* __restrict__ bo,
                             const float* __restrict__ Wu, const float* __restrict__ bu) {
    int idx = blockIdx.x * blockDim.x + threadIdx.x;
    if (idx < G4 * DD) {
        int row = idx >> 9;        // 0..2047
        int col = idx & 511;
        int r = row & 511;
        int g = row >> 9;          // 0=i,1=o,2=u,3=f
        const float* W = (g == 0) ? Wi : (g == 1) ? Wo : (g == 2) ? Wu : Wf;
        const float* src = W + (size_t)r * (DD + HH);
        g_Wx[idx] = to_tf32(src[col]);
        g_Wh[idx] = to_tf32(src[DD + col]);
    }
    if (idx < G4) {
        int g = idx >> 9, r = idx & 511;
        const float* b = (g == 0) ? bi : (g == 1) ? bo : (g == 2) ? bu : bf;
        g_b[idx] = b[r];
    }
}

// ---------------- tf32 tensor-core GEMM ----------------
// C(M x N) = A(M x 512) @ W(N x 512)^T (+bias), N multiple of 128
// CTA tile 128x128x32, 128 threads = 4 warps (2x2), warp tile 64x64
// 2 CTAs/SM co-resident even at ~230 regs (128 thr * 230 = 29.4K regs)
#define SM_STRIDE 36

template <bool PAIR_SUM, bool ADD_BIAS>
__global__ __launch_bounds__(128, 2) void gemm_tc3(const float* __restrict__ A,
                                                   const float* __restrict__ W,
                                                   float* __restrict__ C,
                                                   int M, int N) {
    __shared__ float As[128 * SM_STRIDE];
    __shared__ float Ws[128 * SM_STRIDE];

    const int bm = blockIdx.y * 128;
    const int bn = blockIdx.x * 128;
    const int tid = threadIdx.x;
    const int lane = tid & 31;
    const int wid = tid >> 5;          // 0..3
    const int wm = (wid >> 1) << 6;    // 0 / 64
    const int wn = (wid & 1) << 6;     // 0 / 64
    const int g = lane >> 2;           // 0..7
    const int tig = lane & 3;          // 0..3

    float acc[4][8][4];
#pragma unroll
    for (int mt = 0; mt < 4; mt++)
#pragma unroll
        for (int nt = 0; nt < 8; nt++)
#pragma unroll
            for (int r = 0; r < 4; r++) acc[mt][nt][r] = 0.f;

    for (int k0 = 0; k0 < DD; k0 += 32) {
        // A slab: 128x32 floats = 1024 float4, 128 threads -> 8 iters
#pragma unroll
        for (int i = 0; i < 8; i++) {
            int id = tid + i * 128;
            int row = id >> 3;
            int kq = (id & 7) << 2;
            float4 v = make_float4(0.f, 0.f, 0.f, 0.f);
            if (bm + row < M) {
                if (PAIR_SUM) {
                    const float* p0 = A + (size_t)(2 * (bm + row)) * DD + k0 + kq;
                    float4 a0 = *(const float4*)p0;
                    float4 a1 = *(const float4*)(p0 + DD);
                    v.x = a0.x + a1.x; v.y = a0.y + a1.y;
                    v.z = a0.z + a1.z; v.w = a0.w + a1.w;
                } else {
                    v = *(const float4*)(A + (size_t)(bm + row) * DD + k0 + kq);
                }
                v.x = to_tf32(v.x); v.y = to_tf32(v.y);
                v.z = to_tf32(v.z); v.w = to_tf32(v.w);
            }
            *(float4*)(As + row * SM_STRIDE + kq) = v;
        }
        // W slab: 128x32 floats (pre-rounded at pack)
#pragma unroll
        for (int i = 0; i < 8; i++) {
            int id = tid + i * 128;
            int row = id >> 3;
            int kq = (id & 7) << 2;
            float4 w = *(const float4*)(W + (size_t)(bn + row) * DD + k0 + kq);
            *(float4*)(Ws + row * SM_STRIDE + kq) = w;
        }
        __syncthreads();

#pragma unroll
        for (int ks = 0; ks < 4; ks++) {
            const int kk = ks << 3;
            unsigned int a[4][4];
#pragma unroll
            for (int mt = 0; mt < 4; mt++) {
                int m = wm + (mt << 4) + g;
                a[mt][0] = __float_as_uint(As[m * SM_STRIDE + kk + tig]);
                a[mt][1] = __float_as_uint(As[(m + 8) * SM_STRIDE + kk + tig]);
                a[mt][2] = __float_as_uint(As[m * SM_STRIDE + kk + tig + 4]);
                a[mt][3] = __float_as_uint(As[(m + 8) * SM_STRIDE + kk + tig + 4]);
            }
            unsigned int b[8][2];
#pragma unroll
            for (int nt = 0; nt < 8; nt++) {
                int n = wn + (nt << 3) + g;
                b[nt][0] = __float_as_uint(Ws[n * SM_STRIDE + kk + tig]);
                b[nt][1] = __float_as_uint(Ws[n * SM_STRIDE + kk + tig + 4]);
            }
#pragma unroll
            for (int mt = 0; mt < 4; mt++)
#pragma unroll
                for (int nt = 0; nt < 8; nt++) {
                    float* c = acc[mt][nt];
                    asm volatile(
                        "mma.sync.aligned.m16n8k8.row.col.f32.tf32.tf32.f32 "
                        "{%0,%1,%2,%3}, {%4,%5,%6,%7}, {%8,%9}, {%0,%1,%2,%3};"
                        : "+f"(c[0]), "+f"(c[1]), "+f"(c[2]), "+f"(c[3])
                        : "r"(a[mt][0]), "r"(a[mt][1]), "r"(a[mt][2]), "r"(a[mt][3]),
                          "r"(b[nt][0]), "r"(b[nt][1]));
                }
        }
        __syncthreads();
    }

#pragma unroll
    for (int mt = 0; mt < 4; mt++) {
        int row0 = bm + wm + (mt << 4) + g;
#pragma unroll
        for (int nt = 0; nt < 8; nt++) {
            int col = bn + wn + (nt << 3) + (tig << 1);
            float b0 = 0.f, b1 = 0.f;
            if (ADD_BIAS) { b0 = g_b[col]; b1 = g_b[col + 1]; }
            if (row0 < M) {
                C[(size_t)row0 * N + col]     = acc[mt][nt][0] + b0;
                C[(size_t)row0 * N + col + 1] = acc[mt][nt][1] + b1;
            }
            if (row0 + 8 < M) {
                C[(size_t)(row0 + 8) * N + col]     = acc[mt][nt][2] + b0;
                C[(size_t)(row0 + 8) * N + col + 1] = acc[mt][nt][3] + b1;
            }
        }
    }
}

// ---------------- leaf level (h = 0 children), float4 ----------------
__global__ void leaf_kernel(int start, int cnt) {
    int idx = blockIdx.x * blockDim.x + threadIdx.x;
    if (idx >= cnt * (HH / 4)) return;
    int b = idx >> 7, j4 = (idx & 127) << 2;
    size_t n = (size_t)(start + b);
    const float* Pp = g_P + n * G4;
    float4 pi = *(const float4*)(Pp + j4);
    float4 po = *(const float4*)(Pp + HH + j4);
    float4 pu = *(const float4*)(Pp + 2 * HH + j4);
    float4 c, h;
    {
        float i0 = sig_fast(pi.x), o0 = sig_fast(po.x), u0 = tanh_fast(pu.x);
        c.x = i0 * u0; h.x = o0 * tanh_fast(c.x);
        float i1 = sig_fast(pi.y), o1 = sig_fast(po.y), u1 = tanh_fast(pu.y);
        c.y = i1 * u1; h.y = o1 * tanh_fast(c.y);
        float i2 = sig_fast(pi.z), o2 = sig_fast(po.z), u2 = tanh_fast(pu.z);
        c.z = i2 * u2; h.z = o2 * tanh_fast(c.z);
        float i3 = sig_fast(pi.w), o3 = sig_fast(po.w), u3 = tanh_fast(pu.w);
        c.w = i3 * u3; h.w = o3 * tanh_fast(c.w);
    }
    *(float4*)(g_c + n * HH + j4) = c;
    *(float4*)(g_h + n * HH + j4) = h;
}

// ---------------- internal level combine, float4 ----------------
__global__ void combine_kernel(int start, int cnt, int cs) {
    int idx = blockIdx.x * blockDim.x + threadIdx.x;
    if (idx >= cnt * (HH / 4)) return;
    int b = idx >> 7, j4 = (idx & 127) << 2;
    size_t n = (size_t)(start + b);
    const float* Pp = g_P + n * G4;
    const float* Gi = g_Giou + (size_t)b * (3 * HH);
    float4 pi = *(const float4*)(Pp + j4);
    float4 po = *(const float4*)(Pp + HH + j4);
    float4 pu = *(const float4*)(Pp + 2 * HH + j4);
    float4 pf = *(const float4*)(Pp + 3 * HH + j4);
    float4 gi = *(const float4*)(Gi + j4);
    float4 go = *(const float4*)(Gi + HH + j4);
    float4 gu = *(const float4*)(Gi + 2 * HH + j4);
    float4 gfl = *(const float4*)(g_Gf + (size_t)(2 * b) * HH + j4);
    float4 gfr = *(const float4*)(g_Gf + (size_t)(2 * b + 1) * HH + j4);
    float4 cl = *(const float4*)(g_c + (size_t)(cs + 2 * b) * HH + j4);
    float4 cr = *(const float4*)(g_c + (size_t)(cs + 2 * b + 1) * HH + j4);
    float4 c, h;
#define COMB(X)                                                          \
    {                                                                    \
        float i_ = sig_fast(pi.X + gi.X);                                \
        float o_ = sig_fast(po.X + go.X);                                \
        float u_ = tanh_fast(pu.X + gu.X);                               \
        float fl_ = sig_fast(pf.X + gfl.X);                              \
        float fr_ = sig_fast(pf.X + gfr.X);                              \
        c.X = i_ * u_ + fl_ * cl.X + fr_ * cr.X;                         \
        h.X = o_ * tanh_fast(c.X);                                       \
    }
    COMB(x) COMB(y) COMB(z) COMB(w)
#undef COMB
    *(float4*)(g_c + n * HH + j4) = c;
    *(float4*)(g_h + n * HH + j4) = h;
}

// ---------------- output: [h[0] | c[0]] ----------------
__global__ void write_out(float* __restrict__ out, int out_size) {
    int j = blockIdx.x * blockDim.x + threadIdx.x;
    if (j < HH && j < out_size) out[j] = g_h[j];
    int j2 = j + HH;
    if (j < HH && j2 < out_size) out[j2] = g_c[j];
}

extern "C" void kernel_launch(void* const* d_in, const int* in_sizes, int n_in,
                              void* d_out, int out_size) {
    const float* x  = (const float*)d_in[0];
    const float* Wi = (const float*)d_in[1];
    const float* bi = (const float*)d_in[2];
    const float* Wf = (const float*)d_in[3];
    const float* bf = (const float*)d_in[4];
    const float* Wo = (const float*)d_in[5];
    const float* bo = (const float*)d_in[6];
    const float* Wu = (const float*)d_in[7];
    const float* bu = (const float*)d_in[8];
    float* out = (float*)d_out;

    float *pP, *pGiou, *pGf, *ph, *pWx, *pWh;
    cudaGetSymbolAddress((void**)&pP,    g_P);
    cudaGetSymbolAddress((void**)&pGiou, g_Giou);
    cudaGetSymbolAddress((void**)&pGf,   g_Gf);
    cudaGetSymbolAddress((void**)&ph,    g_h);
    cudaGetSymbolAddress((void**)&pWx,   g_Wx);
    cudaGetSymbolAddress((void**)&pWh,   g_Wh);

    pack_weights<<<(G4 * DD + 255) / 256, 256>>>(Wi, bi, Wf, bf, Wo, bo, Wu, bu);

    // P = x @ Wx^T + b, all nodes
    {
        dim3 grid(G4 / 128, (N_NODES + 127) / 128);
        gemm_tc3<false, true><<<grid, 128>>>(x, pWx, pP, N_NODES, G4);
    }

    // leaves
    {
        int start = (1 << (DEPTH - 1)) - 1;
        int cnt = 1 << (DEPTH - 1);
        leaf_kernel<<<(cnt * (HH / 4) + 255) / 256, 256>>>(start, cnt);
    }

    // internal levels
    for (int lvl = DEPTH - 2; lvl >= 0; lvl--) {
        int start = (1 << lvl) - 1;
        int cnt = 1 << lvl;
        int cs = 2 * start + 1;
        const float* hchild = ph + (size_t)cs * HH;

        // iou gates on pair-summed h: M=cnt, N=1536
        {
            dim3 grid(1536 / 128, (cnt + 127) / 128);
            gemm_tc3<true, false><<<grid, 128>>>(hchild, pWh, pGiou, cnt, 1536);
        }
        // f gate on raw children: M=2*cnt, N=512
        {
            int Mf = 2 * cnt;
            const float* Wf_h = pWh + (size_t)(3 * HH) * DD;
            dim3 grid(512 / 128, (Mf + 127) / 128);
            gemm_tc3<false, false><<<grid, 128>>>(hchild, Wf_h, pGf, Mf, 512);
        }
        combine_kernel<<<(cnt * (HH / 4) + 255) / 256, 256>>>(start, cnt, cs);
    }

    write_out<<<(2 * HH + 255) / 256, 256>>>(out, out_size);
}

// round 6
// speedup vs baseline: 1.9940x; 1.9940x over previous
#include <cuda_runtime.h>
#include <cstdint>
#include <stdint.h>
#include <math.h>

#define DEPTH 15
#define N_NODES ((1 << DEPTH) - 1)   // 32767
#define DD 512
#define HH 512
#define G4 (4 * HH)                  // 2048 gate cols, packed [i | o | u | f]
#define SM_STRIDE 36
#define BUF (128 * SM_STRIDE)        // floats per A-or-W slab

// ---------------- scratch (device globals; allocation-free) ----------------
__device__ float g_P[(size_t)N_NODES * G4];                   // x-part + bias, all gates
__device__ float g_Giou[(size_t)(1 << (DEPTH - 2)) * 3 * HH]; // parent-indexed iou h-part
__device__ float g_Gf[(size_t)(1 << (DEPTH - 1)) * HH];       // child-indexed f h-part
__device__ float g_h[(size_t)N_NODES * HH];                   // tf32-rounded h (GEMM input)
__device__ float g_c[(size_t)N_NODES * HH];                   // full-precision c
__device__ float g_hs[(size_t)(1 << (DEPTH - 2)) * HH];       // pair-summed h (rounded)
__device__ float g_xr[(size_t)N_NODES * DD];                  // tf32-rounded x
__device__ float g_h0[HH];                                    // full-precision h of node 0
__device__ float g_Wx[(size_t)G4 * DD];                       // [i|o|u|f] x-cols (rounded)
__device__ float g_Wh[(size_t)G4 * HH];                       // [i|o|u|f] h-cols (rounded)
__device__ float g_b[G4];

// ---------------- helpers ----------------
__device__ __forceinline__ float tanh_fast(float x) {
    float y;
    asm("tanh.approx.f32 %0, %1;" : "=f"(y) : "f"(x));
    return y;
}
__device__ __forceinline__ float sig_fast(float x) {
    return 0.5f * tanh_fast(0.5f * x) + 0.5f;
}
__device__ __forceinline__ float to_tf32(float x) {
    unsigned int r;
    asm("cvt.rna.tf32.f32 %0, %1;" : "=r"(r) : "f"(x));
    return __uint_as_float(r);
}

// ---------------- pack weights, order [i|o|u|f] ----------------
__global__ void pack_weights(const float* __restrict__ Wi, const float* __restrict__ bi,
                             const float* __restrict__ Wf, const float* __restrict__ bf,
                             const float* __restrict__ Wo, const float* __restrict__ bo,
                             const float* __restrict__ Wu, const float* __restrict__ bu) {
    int idx = blockIdx.x * blockDim.x + threadIdx.x;
    if (idx < G4 * DD) {
        int row = idx >> 9;
        int col = idx & 511;
        int r = row & 511;
        int g = row >> 9;          // 0=i,1=o,2=u,3=f
        const float* W = (g == 0) ? Wi : (g == 1) ? Wo : (g == 2) ? Wu : Wf;
        const float* src = W + (size_t)r * (DD + HH);
        g_Wx[idx] = to_tf32(src[col]);
        g_Wh[idx] = to_tf32(src[DD + col]);
    }
    if (idx < G4) {
        int g = idx >> 9, r = idx & 511;
        const float* b = (g == 0) ? bi : (g == 1) ? bo : (g == 2) ? bu : bf;
        g_b[idx] = b[r];
    }
}

// ---------------- round x to tf32 ----------------
__global__ void round_x(const float* __restrict__ x, float* __restrict__ xr, int n4) {
    int idx = blockIdx.x * blockDim.x + threadIdx.x;
    if (idx >= n4) return;
    float4 v = *(const float4*)(x + (size_t)idx * 4);
    v.x = to_tf32(v.x); v.y = to_tf32(v.y); v.z = to_tf32(v.z); v.w = to_tf32(v.w);
    *(float4*)(xr + (size_t)idx * 4) = v;
}

// ---------------- pair-sum of sibling h (rounded) ----------------
__global__ void hsum_kernel(const float* __restrict__ hin, float* __restrict__ hs, int cnt) {
    int idx = blockIdx.x * blockDim.x + threadIdx.x;
    if (idx >= cnt * (HH / 4)) return;
    int b = idx >> 7, j4 = (idx & 127) << 2;
    float4 a = *(const float4*)(hin + (size_t)(2 * b) * HH + j4);
    float4 c = *(const float4*)(hin + (size_t)(2 * b + 1) * HH + j4);
    float4 s;
    s.x = to_tf32(a.x + c.x); s.y = to_tf32(a.y + c.y);
    s.z = to_tf32(a.z + c.z); s.w = to_tf32(a.w + c.w);
    *(float4*)(hs + (size_t)b * HH + j4) = s;
}

// ---------------- cp.async-pipelined tf32 GEMM ----------------
// C(M x N) = A(M x 512) @ W(N x 512)^T (+bias). A,W pre-rounded tf32 in gmem.
// CTA 128x128x32, 256 thr, 8 warps (2x4), warp tile 64x32, 2-stage cp.async.
template <bool ADD_BIAS>
__global__ __launch_bounds__(256, 2) void gemm_cp(const float* __restrict__ A,
                                                  const float* __restrict__ W,
                                                  float* __restrict__ C, int M, int N) {
    extern __shared__ float smem[];   // [buf0 A | buf0 W | buf1 A | buf1 W]
    const int bm = blockIdx.y * 128;
    const int bn = blockIdx.x * 128;
    const int tid = threadIdx.x;
    const int lane = tid & 31;
    const int wid = tid >> 5;
    const int wm = (wid >> 2) << 6;   // 0 / 64
    const int wn = (wid & 3) << 5;    // 0 / 32 / 64 / 96
    const int g = lane >> 2;
    const int tig = lane & 3;

    float acc[4][4][4];
#pragma unroll
    for (int mt = 0; mt < 4; mt++)
#pragma unroll
        for (int nt = 0; nt < 4; nt++)
#pragma unroll
            for (int r = 0; r < 4; r++) acc[mt][nt][r] = 0.f;

    // per-thread copy slot (same for A and W): 4 chunks of 16B each
    const int c_row = tid >> 3;            // base rows: tid>>3 then +32 per iter? No:
    // id = tid + i*256 -> row = id>>3 = (tid>>3) + i*32, kq = (tid&7)<<2
    const int c_kq = (tid & 7) << 2;

#define ISSUE_STAGE(S, K0)                                                        \
    {                                                                             \
        unsigned int sb = (unsigned int)__cvta_generic_to_shared(                 \
            smem + ((S) & 1) * 2 * BUF);                                          \
        _Pragma("unroll")                                                         \
        for (int i = 0; i < 4; i++) {                                             \
            int row = c_row + i * 32;                                             \
            int gr = bm + row;                                                    \
            int zf = (gr < M) ? 16 : 0;                                           \
            const float* src = A + (size_t)(zf ? gr : 0) * DD + (K0) + c_kq;      \
            asm volatile("cp.async.cg.shared.global [%0], [%1], 16, %2;"          \
                         :: "r"(sb + (unsigned)(row * SM_STRIDE + c_kq) * 4),     \
                            "l"(src), "r"(zf));                                   \
        }                                                                         \
        unsigned int sbw = sb + BUF * 4;                                          \
        _Pragma("unroll")                                                         \
        for (int i = 0; i < 4; i++) {                                             \
            int row = c_row + i * 32;                                             \
            const float* src = W + (size_t)(bn + row) * DD + (K0) + c_kq;         \
            asm volatile("cp.async.cg.shared.global [%0], [%1], 16;"              \
                         :: "r"(sbw + (unsigned)(row * SM_STRIDE + c_kq) * 4),    \
                            "l"(src));                                            \
        }                                                                         \
        asm volatile("cp.async.commit_group;");                                   \
    }

    ISSUE_STAGE(0, 0)

    for (int s = 0; s < 16; s++) {
        if (s + 1 < 16) {
            ISSUE_STAGE(s + 1, (s + 1) * 32)
            asm volatile("cp.async.wait_group 1;");
        } else {
            asm volatile("cp.async.wait_group 0;");
        }
        __syncthreads();

        const float* As = smem + (s & 1) * 2 * BUF;
        const float* Ws = As + BUF;
#pragma unroll
        for (int ks = 0; ks < 4; ks++) {
            const int kk = ks << 3;
            unsigned int a[4][4];
#pragma unroll
            for (int mt = 0; mt < 4; mt++) {
                int m = wm + (mt << 4) + g;
                a[mt][0] = __float_as_uint(As[m * SM_STRIDE + kk + tig]);
                a[mt][1] = __float_as_uint(As[(m + 8) * SM_STRIDE + kk + tig]);
                a[mt][2] = __float_as_uint(As[m * SM_STRIDE + kk + tig + 4]);
                a[mt][3] = __float_as_uint(As[(m + 8) * SM_STRIDE + kk + tig + 4]);
            }
            unsigned int b[4][2];
#pragma unroll
            for (int nt = 0; nt < 4; nt++) {
                int n = wn + (nt << 3) + g;
                b[nt][0] = __float_as_uint(Ws[n * SM_STRIDE + kk + tig]);
                b[nt][1] = __float_as_uint(Ws[n * SM_STRIDE + kk + tig + 4]);
            }
#pragma unroll
            for (int mt = 0; mt < 4; mt++)
#pragma unroll
                for (int nt = 0; nt < 4; nt++) {
                    float* c = acc[mt][nt];
                    asm volatile(
                        "mma.sync.aligned.m16n8k8.row.col.f32.tf32.tf32.f32 "
                        "{%0,%1,%2,%3}, {%4,%5,%6,%7}, {%8,%9}, {%0,%1,%2,%3};"
                        : "+f"(c[0]), "+f"(c[1]), "+f"(c[2]), "+f"(c[3])
                        : "r"(a[mt][0]), "r"(a[mt][1]), "r"(a[mt][2]), "r"(a[mt][3]),
                          "r"(b[nt][0]), "r"(b[nt][1]));
                }
        }
        __syncthreads();
    }

#pragma unroll
    for (int mt = 0; mt < 4; mt++) {
        int row0 = bm + wm + (mt << 4) + g;
#pragma unroll
        for (int nt = 0; nt < 4; nt++) {
            int col = bn + wn + (nt << 3) + (tig << 1);
            float b0 = 0.f, b1 = 0.f;
            if (ADD_BIAS) { b0 = g_b[col]; b1 = g_b[col + 1]; }
            if (row0 < M) {
                C[(size_t)row0 * N + col]     = acc[mt][nt][0] + b0;
                C[(size_t)row0 * N + col + 1] = acc[mt][nt][1] + b1;
            }
            if (row0 + 8 < M) {
                C[(size_t)(row0 + 8) * N + col]     = acc[mt][nt][2] + b0;
                C[(size_t)(row0 + 8) * N + col + 1] = acc[mt][nt][3] + b1;
            }
        }
    }
#undef ISSUE_STAGE
}

// ---------------- leaf level (h = 0 children) ----------------
__global__ void leaf_kernel(int start, int cnt) {
    int idx = blockIdx.x * blockDim.x + threadIdx.x;
    if (idx >= cnt * (HH / 4)) return;
    int b = idx >> 7, j4 = (idx & 127) << 2;
    size_t n = (size_t)(start + b);
    const float* Pp = g_P + n * G4;
    float4 pi = *(const float4*)(Pp + j4);
    float4 po = *(const float4*)(Pp + HH + j4);
    float4 pu = *(const float4*)(Pp + 2 * HH + j4);
    float4 c, h;
#define LEAF1(X)                                                     \
    {                                                                \
        float i_ = sig_fast(pi.X), o_ = sig_fast(po.X);              \
        float u_ = tanh_fast(pu.X);                                  \
        c.X = i_ * u_;                                               \
        h.X = to_tf32(o_ * tanh_fast(c.X));                          \
    }
    LEAF1(x) LEAF1(y) LEAF1(z) LEAF1(w)
#undef LEAF1
    *(float4*)(g_c + n * HH + j4) = c;
    *(float4*)(g_h + n * HH + j4) = h;
}

// ---------------- internal level combine ----------------
__global__ void combine_kernel(int start, int cnt, int cs) {
    int idx = blockIdx.x * blockDim.x + threadIdx.x;
    if (idx >= cnt * (HH / 4)) return;
    int b = idx >> 7, j4 = (idx & 127) << 2;
    size_t n = (size_t)(start + b);
    const float* Pp = g_P + n * G4;
    const float* Gi = g_Giou + (size_t)b * (3 * HH);
    float4 pi = *(const float4*)(Pp + j4);
    float4 po = *(const float4*)(Pp + HH + j4);
    float4 pu = *(const float4*)(Pp + 2 * HH + j4);
    float4 pf = *(const float4*)(Pp + 3 * HH + j4);
    float4 gi = *(const float4*)(Gi + j4);
    float4 go = *(const float4*)(Gi + HH + j4);
    float4 gu = *(const float4*)(Gi + 2 * HH + j4);
    float4 gfl = *(const float4*)(g_Gf + (size_t)(2 * b) * HH + j4);
    float4 gfr = *(const float4*)(g_Gf + (size_t)(2 * b + 1) * HH + j4);
    float4 cl = *(const float4*)(g_c + (size_t)(cs + 2 * b) * HH + j4);
    float4 cr = *(const float4*)(g_c + (size_t)(cs + 2 * b + 1) * HH + j4);
    float4 c, h, hfull;
#define COMB(X)                                                      \
    {                                                                \
        float i_ = sig_fast(pi.X + gi.X);                            \
        float o_ = sig_fast(po.X + go.X);                            \
        float u_ = tanh_fast(pu.X + gu.X);                           \
        float fl_ = sig_fast(pf.X + gfl.X);                          \
        float fr_ = sig_fast(pf.X + gfr.X);                          \
        c.X = i_ * u_ + fl_ * cl.X + fr_ * cr.X;                     \
        hfull.X = o_ * tanh_fast(c.X);                               \
        h.X = to_tf32(hfull.X);                                      \
    }
    COMB(x) COMB(y) COMB(z) COMB(w)
#undef COMB
    *(float4*)(g_c + n * HH + j4) = c;
    *(float4*)(g_h + n * HH + j4) = h;
    if (n == 0) *(float4*)(g_h0 + j4) = hfull;   // full-precision h for output
}

// ---------------- output: [h[0] | c[0]] ----------------
__global__ void write_out(float* __restrict__ out, int out_size) {
    int j = blockIdx.x * blockDim.x + threadIdx.x;
    if (j < HH && j < out_size) out[j] = g_h0[j];
    int j2 = j + HH;
    if (j < HH && j2 < out_size) out[j2] = g_c[j];
}

extern "C" void kernel_launch(void* const* d_in, const int* in_sizes, int n_in,
                              void* d_out, int out_size) {
    const float* x  = (const float*)d_in[0];
    const float* Wi = (const float*)d_in[1];
    const float* bi = (const float*)d_in[2];
    const float* Wf = (const float*)d_in[3];
    const float* bf = (const float*)d_in[4];
    const float* Wo = (const float*)d_in[5];
    const float* bo = (const float*)d_in[6];
    const float* Wu = (const float*)d_in[7];
    const float* bu = (const float*)d_in[8];
    float* out = (float*)d_out;

    float *pP, *pGiou, *pGf, *ph, *phs, *pxr, *pWx, *pWh;
    cudaGetSymbolAddress((void**)&pP,    g_P);
    cudaGetSymbolAddress((void**)&pGiou, g_Giou);
    cudaGetSymbolAddress((void**)&pGf,   g_Gf);
    cudaGetSymbolAddress((void**)&ph,    g_h);
    cudaGetSymbolAddress((void**)&phs,   g_hs);
    cudaGetSymbolAddress((void**)&pxr,   g_xr);
    cudaGetSymbolAddress((void**)&pWx,   g_Wx);
    cudaGetSymbolAddress((void**)&pWh,   g_Wh);

    const int SMEM_GEMM = 4 * BUF * 4;   // 73728 B
    cudaFuncSetAttribute(gemm_cp<true>,
                         cudaFuncAttributeMaxDynamicSharedMemorySize, SMEM_GEMM);
    cudaFuncSetAttribute(gemm_cp<false>,
                         cudaFuncAttributeMaxDynamicSharedMemorySize, SMEM_GEMM);

    pack_weights<<<(G4 * DD + 255) / 256, 256>>>(Wi, bi, Wf, bf, Wo, bo, Wu, bu);
    round_x<<<(N_NODES * (DD / 4) + 255) / 256, 256>>>(x, pxr, N_NODES * (DD / 4));

    // P = x @ Wx^T + b, all nodes
    {
        dim3 grid(G4 / 128, (N_NODES + 127) / 128);
        gemm_cp<true><<<grid, 256, SMEM_GEMM>>>(pxr, pWx, pP, N_NODES, G4);
    }

    // leaves
    {
        int start = (1 << (DEPTH - 1)) - 1;
        int cnt = 1 << (DEPTH - 1);
        leaf_kernel<<<(cnt * (HH / 4) + 255) / 256, 256>>>(start, cnt);
    }

    // internal levels
    for (int lvl = DEPTH - 2; lvl >= 0; lvl--) {
        int start = (1 << lvl) - 1;
        int cnt = 1 << lvl;
        int cs = 2 * start + 1;
        const float* hchild = ph + (size_t)cs * HH;

        // pair-sum siblings
        hsum_kernel<<<(cnt * (HH / 4) + 255) / 256, 256>>>(hchild, phs, cnt);
        // iou gates on h-sums: M=cnt, N=1536
        {
            dim3 grid(1536 / 128, (cnt + 127) / 128);
            gemm_cp<false><<<grid, 256, SMEM_GEMM>>>(phs, pWh, pGiou, cnt, 1536);
        }
        // f gate on raw children: M=2*cnt, N=512
        {
            int Mf = 2 * cnt;
            const float* Wf_h = pWh + (size_t)(3 * HH) * DD;
            dim3 grid(512 / 128, (Mf + 127) / 128);
            gemm_cp<false><<<grid, 256, SMEM_GEMM>>>(hchild, Wf_h, pGf, Mf, 512);
        }
        combine_kernel<<<(cnt * (HH / 4) + 255) / 256, 256>>>(start, cnt, cs);
    }

    write_out<<<(2 * HH + 255) / 256, 256>>>(out, out_size);
}

// round 7
// speedup vs baseline: 2.3497x; 1.1784x over previous
#include <cuda_runtime.h>
#include <cstdint>
#include <stdint.h>

#define DEPTH 15
#define N_NODES ((1 << DEPTH) - 1)   // 32767
#define DD 512
#define HH 512
#define G4 2048                      // gate cols packed [i | o | u | f]
#define SM_STRIDE 36
#define BUF (128 * SM_STRIDE)
#define NCTA_PERS 128

// ---------------- scratch ----------------
__device__ float g_P[(size_t)N_NODES * G4];
__device__ float g_Giou[(size_t)8192 * 1536];
__device__ float g_Gf[(size_t)16384 * HH];
__device__ float g_h[(size_t)N_NODES * HH];     // tf32-rounded h
__device__ float g_c[(size_t)N_NODES * HH];     // full-precision c
__device__ float g_hs[(size_t)8192 * HH];       // pair-summed h (rounded)
__device__ float g_xr[(size_t)N_NODES * DD];    // tf32-rounded x
__device__ float g_h0[HH];                      // full-precision h of node 0
__device__ float g_Wx[(size_t)G4 * DD];
__device__ float g_Wh[(size_t)G4 * HH];
__device__ float g_b[G4];
__device__ unsigned int g_bar_cnt;              // zero-init; self-resetting
__device__ unsigned int g_bar_rel;              // monotonic

// ---------------- helpers ----------------
__device__ __forceinline__ float tanh_fast(float x) {
    float y;
    asm("tanh.approx.f32 %0, %1;" : "=f"(y) : "f"(x));
    return y;
}
__device__ __forceinline__ float sig_fast(float x) {
    return 0.5f * tanh_fast(0.5f * x) + 0.5f;
}
__device__ __forceinline__ float to_tf32(float x) {
    unsigned int r;
    asm("cvt.rna.tf32.f32 %0, %1;" : "=r"(r) : "f"(x));
    return __uint_as_float(r);
}

// ---------------- pack weights [i|o|u|f] ----------------
__global__ void pack_weights(const float* __restrict__ Wi, const float* __restrict__ bi,
                             const float* __restrict__ Wf, const float* __restrict__ bf,
                             const float* __restrict__ Wo, const float* __restrict__ bo,
                             const float* __restrict__ Wu, const float* __restrict__ bu) {
    int idx = blockIdx.x * blockDim.x + threadIdx.x;
    if (idx < G4 * DD) {
        int row = idx >> 9;
        int col = idx & 511;
        int r = row & 511;
        int g = row >> 9;          // 0=i,1=o,2=u,3=f
        const float* W = (g == 0) ? Wi : (g == 1) ? Wo : (g == 2) ? Wu : Wf;
        const float* src = W + (size_t)r * (DD + HH);
        g_Wx[idx] = to_tf32(src[col]);
        g_Wh[idx] = to_tf32(src[DD + col]);
    }
    if (idx < G4) {
        int g = idx >> 9, r = idx & 511;
        const float* b = (g == 0) ? bi : (g == 1) ? bo : (g == 2) ? bu : bf;
        g_b[idx] = b[r];
    }
}

// ---------------- round x to tf32 ----------------
__global__ void round_x(const float* __restrict__ x, float* __restrict__ xr, int n4) {
    int idx = blockIdx.x * blockDim.x + threadIdx.x;
    if (idx >= n4) return;
    float4 v = *(const float4*)(x + (size_t)idx * 4);
    v.x = to_tf32(v.x); v.y = to_tf32(v.y); v.z = to_tf32(v.z); v.w = to_tf32(v.w);
    *(float4*)(xr + (size_t)idx * 4) = v;
}

// ---------------- cp.async tf32 GEMM tile (device fn) ----------------
// C[bm:bm+128, bn:bn+128] = A(M x 512) @ W(rows x 512)^T, row stride ldC, opt bias
__device__ __forceinline__ void gemm_tile(const float* __restrict__ A,
                                          const float* __restrict__ W,
                                          float* __restrict__ C,
                                          int M, int ldC,
                                          const float* __restrict__ bias,
                                          int bm, int bn, float* smem) {
    const int tid = threadIdx.x;
    const int lane = tid & 31;
    const int wid = tid >> 5;
    const int wm = (wid >> 2) << 6;   // 0 / 64
    const int wn = (wid & 3) << 5;    // 0 / 32 / 64 / 96
    const int g = lane >> 2;
    const int tig = lane & 3;
    const int c_row = tid >> 3;
    const int c_kq = (tid & 7) << 2;

    float acc[4][4][4];
#pragma unroll
    for (int mt = 0; mt < 4; mt++)
#pragma unroll
        for (int nt = 0; nt < 4; nt++)
#pragma unroll
            for (int r = 0; r < 4; r++) acc[mt][nt][r] = 0.f;

    auto issue = [&](int S, int K0) {
        unsigned int sb = (unsigned int)__cvta_generic_to_shared(smem + (S & 1) * 2 * BUF);
#pragma unroll
        for (int i = 0; i < 4; i++) {
            int row = c_row + i * 32;
            int gr = bm + row;
            int zf = (gr < M) ? 16 : 0;
            const float* src = A + (size_t)(zf ? gr : 0) * DD + K0 + c_kq;
            asm volatile("cp.async.cg.shared.global [%0], [%1], 16, %2;"
                         :: "r"(sb + (unsigned)(row * SM_STRIDE + c_kq) * 4),
                            "l"(src), "r"(zf));
        }
        unsigned int sbw = sb + BUF * 4;
#pragma unroll
        for (int i = 0; i < 4; i++) {
            int row = c_row + i * 32;
            const float* src = W + (size_t)(bn + row) * DD + K0 + c_kq;
            asm volatile("cp.async.cg.shared.global [%0], [%1], 16;"
                         :: "r"(sbw + (unsigned)(row * SM_STRIDE + c_kq) * 4),
                            "l"(src));
        }
        asm volatile("cp.async.commit_group;");
    };

    issue(0, 0);
    for (int s = 0; s < 16; s++) {
        if (s + 1 < 16) {
            issue(s + 1, (s + 1) * 32);
            asm volatile("cp.async.wait_group 1;");
        } else {
            asm volatile("cp.async.wait_group 0;");
        }
        __syncthreads();

        const float* As = smem + (s & 1) * 2 * BUF;
        const float* Ws = As + BUF;
#pragma unroll
        for (int ks = 0; ks < 4; ks++) {
            const int kk = ks << 3;
            unsigned int a[4][4];
#pragma unroll
            for (int mt = 0; mt < 4; mt++) {
                int m = wm + (mt << 4) + g;
                a[mt][0] = __float_as_uint(As[m * SM_STRIDE + kk + tig]);
                a[mt][1] = __float_as_uint(As[(m + 8) * SM_STRIDE + kk + tig]);
                a[mt][2] = __float_as_uint(As[m * SM_STRIDE + kk + tig + 4]);
                a[mt][3] = __float_as_uint(As[(m + 8) * SM_STRIDE + kk + tig + 4]);
            }
            unsigned int b[4][2];
#pragma unroll
            for (int nt = 0; nt < 4; nt++) {
                int n = wn + (nt << 3) + g;
                b[nt][0] = __float_as_uint(Ws[n * SM_STRIDE + kk + tig]);
                b[nt][1] = __float_as_uint(Ws[n * SM_STRIDE + kk + tig + 4]);
            }
#pragma unroll
            for (int mt = 0; mt < 4; mt++)
#pragma unroll
                for (int nt = 0; nt < 4; nt++) {
                    float* c = acc[mt][nt];
                    asm volatile(
                        "mma.sync.aligned.m16n8k8.row.col.f32.tf32.tf32.f32 "
                        "{%0,%1,%2,%3}, {%4,%5,%6,%7}, {%8,%9}, {%0,%1,%2,%3};"
                        : "+f"(c[0]), "+f"(c[1]), "+f"(c[2]), "+f"(c[3])
                        : "r"(a[mt][0]), "r"(a[mt][1]), "r"(a[mt][2]), "r"(a[mt][3]),
                          "r"(b[nt][0]), "r"(b[nt][1]));
                }
        }
        __syncthreads();
    }

#pragma unroll
    for (int mt = 0; mt < 4; mt++) {
        int row0 = bm + wm + (mt << 4) + g;
#pragma unroll
        for (int nt = 0; nt < 4; nt++) {
            int col = bn + wn + (nt << 3) + (tig << 1);
            float b0 = 0.f, b1 = 0.f;
            if (bias) { b0 = bias[col]; b1 = bias[col + 1]; }
            if (row0 < M) {
                C[(size_t)row0 * ldC + col]     = acc[mt][nt][0] + b0;
                C[(size_t)row0 * ldC + col + 1] = acc[mt][nt][1] + b1;
            }
            if (row0 + 8 < M) {
                C[(size_t)(row0 + 8) * ldC + col]     = acc[mt][nt][2] + b0;
                C[(size_t)(row0 + 8) * ldC + col + 1] = acc[mt][nt][3] + b1;
            }
        }
    }
}

__global__ __launch_bounds__(256, 2) void gemm_cp(const float* __restrict__ A,
                                                  const float* __restrict__ W,
                                                  float* __restrict__ C,
                                                  int M, int ldC,
                                                  const float* __restrict__ bias) {
    extern __shared__ float smem[];
    gemm_tile(A, W, C, M, ldC, bias, blockIdx.y * 128, blockIdx.x * 128, smem);
}

// ---------------- combine unit (fused pair-sum), shared by kernels ----------
__device__ __forceinline__ void combine_unit(int u, int U, int start, int cs,
                                             bool write_hs, float4* sh) {
    float4 h4 = make_float4(0.f, 0.f, 0.f, 0.f);
    int b = u >> 7, j4 = (u & 127) << 2;
    if (u < U) {
        size_t n = (size_t)(start + b);
        const float* Pp = g_P + n * G4;
        const float* Gi = g_Giou + (size_t)b * 1536;
        float4 pi = *(const float4*)(Pp + j4);
        float4 po = *(const float4*)(Pp + HH + j4);
        float4 pu = *(const float4*)(Pp + 2 * HH + j4);
        float4 pf = *(const float4*)(Pp + 3 * HH + j4);
        float4 gi = *(const float4*)(Gi + j4);
        float4 go = *(const float4*)(Gi + HH + j4);
        float4 gu = *(const float4*)(Gi + 2 * HH + j4);
        float4 gfl = *(const float4*)(g_Gf + (size_t)(2 * b) * HH + j4);
        float4 gfr = *(const float4*)(g_Gf + (size_t)(2 * b + 1) * HH + j4);
        float4 cl = *(const float4*)(g_c + (size_t)(cs + 2 * b) * HH + j4);
        float4 cr = *(const float4*)(g_c + (size_t)(cs + 2 * b + 1) * HH + j4);
        float4 c4, hfull;
#define COMB(X)                                                  \
        {                                                        \
            float i_ = sig_fast(pi.X + gi.X);                    \
            float o_ = sig_fast(po.X + go.X);                    \
            float u_ = tanh_fast(pu.X + gu.X);                   \
            float fl_ = sig_fast(pf.X + gfl.X);                  \
            float fr_ = sig_fast(pf.X + gfr.X);                  \
            c4.X = i_ * u_ + fl_ * cl.X + fr_ * cr.X;            \
            hfull.X = o_ * tanh_fast(c4.X);                      \
            h4.X = to_tf32(hfull.X);                             \
        }
        COMB(x) COMB(y) COMB(z) COMB(w)
#undef COMB
        *(float4*)(g_c + n * HH + j4) = c4;
        *(float4*)(g_h + n * HH + j4) = h4;
        if (n == 0) *(float4*)(g_h0 + j4) = hfull;
    }
    sh[threadIdx.x] = h4;
    __syncthreads();
    if (write_hs && threadIdx.x < 128 && u < U) {
        float4 o = sh[threadIdx.x + 128];
        float4 s;
        s.x = to_tf32(h4.x + o.x); s.y = to_tf32(h4.y + o.y);
        s.z = to_tf32(h4.z + o.z); s.w = to_tf32(h4.w + o.w);
        *(float4*)(g_hs + (size_t)(b >> 1) * HH + j4) = s;
    }
    __syncthreads();
}

// ---------------- big-level combine ----------------
__global__ void combine_big(int start, int cnt, int cs) {
    __shared__ float4 sh[256];
    int u = blockIdx.x * 256 + threadIdx.x;
    combine_unit(u, cnt << 7, start, cs, true, sh);
}

// ---------------- leaf level (+ fused pair-sum) ----------------
__global__ void leaf_kernel() {
    __shared__ float4 sh[256];
    int u = blockIdx.x * 256 + threadIdx.x;
    int b = u >> 7, j4 = (u & 127) << 2;
    size_t n = (size_t)((1 << (DEPTH - 1)) - 1 + b);
    const float* Pp = g_P + n * G4;
    float4 pi = *(const float4*)(Pp + j4);
    float4 po = *(const float4*)(Pp + HH + j4);
    float4 pu = *(const float4*)(Pp + 2 * HH + j4);
    float4 c4, h4;
#define LEAF1(X)                                             \
    {                                                        \
        float i_ = sig_fast(pi.X), o_ = sig_fast(po.X);      \
        float u_ = tanh_fast(pu.X);                          \
        c4.X = i_ * u_;                                      \
        h4.X = to_tf32(o_ * tanh_fast(c4.X));                \
    }
    LEAF1(x) LEAF1(y) LEAF1(z) LEAF1(w)
#undef LEAF1
    *(float4*)(g_c + n * HH + j4) = c4;
    *(float4*)(g_h + n * HH + j4) = h4;
    sh[threadIdx.x] = h4;
    __syncthreads();
    if (threadIdx.x < 128) {
        float4 o = sh[threadIdx.x + 128];
        float4 s;
        s.x = to_tf32(h4.x + o.x); s.y = to_tf32(h4.y + o.y);
        s.z = to_tf32(h4.z + o.z); s.w = to_tf32(h4.w + o.w);
        *(float4*)(g_hs + (size_t)(b >> 1) * HH + j4) = s;
    }
}

// ---------------- software grid barrier (replay-safe) ----------------
__device__ __forceinline__ void grid_sync(unsigned int gen, unsigned int rel_base) {
    __syncthreads();
    if (threadIdx.x == 0) {
        __threadfence();
        unsigned int a = atomicAdd(&g_bar_cnt, 1);
        if (a == NCTA_PERS - 1) {
            g_bar_cnt = 0;
            __threadfence();
            atomicAdd(&g_bar_rel, 1);
        } else {
            while (*(volatile unsigned int*)&g_bar_rel - rel_base < gen) { }
        }
        __threadfence();
    }
    __syncthreads();
}

// ---------------- persistent kernel: levels 9..0 ----------------
__global__ __launch_bounds__(256) void small_levels() {
    extern __shared__ float smem[];
    unsigned int rel_base = *(volatile unsigned int*)&g_bar_rel;
    unsigned int gen = 0;
    for (int lvl = 9; lvl >= 0; lvl--) {
        int cnt = 1 << lvl;
        int start = cnt - 1;
        int cs = 2 * cnt - 1;
        int tiles_i = ((cnt + 127) >> 7) * 12;
        int tiles_f = ((2 * cnt + 127) >> 7) * 4;
        int tot = tiles_i + tiles_f;
        for (int t = blockIdx.x; t < tot; t += NCTA_PERS) {
            if (t < tiles_i) {
                int by = t / 12, bx = t % 12;
                gemm_tile(g_hs, g_Wh, g_Giou, cnt, 1536, nullptr,
                          by * 128, bx * 128, smem);
            } else {
                int t2 = t - tiles_i;
                int by = t2 >> 2, bx = t2 & 3;
                gemm_tile(g_h + (size_t)cs * HH, g_Wh + (size_t)(3 * HH) * DD,
                          g_Gf, 2 * cnt, 512, nullptr, by * 128, bx * 128, smem);
            }
        }
        gen++; grid_sync(gen, rel_base);
        int U = cnt << 7;
        for (int base = blockIdx.x * 256; base < U; base += NCTA_PERS * 256) {
            combine_unit(base + (int)threadIdx.x, U, start, cs, lvl > 0,
                         (float4*)smem);
        }
        gen++; grid_sync(gen, rel_base);
    }
}

// ---------------- output: [h[0] | c[0]] ----------------
__global__ void write_out(float* __restrict__ out, int out_size) {
    int j = blockIdx.x * blockDim.x + threadIdx.x;
    if (j < HH && j < out_size) out[j] = g_h0[j];
    int j2 = j + HH;
    if (j < HH && j2 < out_size) out[j2] = g_c[j];
}

extern "C" void kernel_launch(void* const* d_in, const int* in_sizes, int n_in,
                              void* d_out, int out_size) {
    const float* x  = (const float*)d_in[0];
    const float* Wi = (const float*)d_in[1];
    const float* bi = (const float*)d_in[2];
    const float* Wf = (const float*)d_in[3];
    const float* bf = (const float*)d_in[4];
    const float* Wo = (const float*)d_in[5];
    const float* bo = (const float*)d_in[6];
    const float* Wu = (const float*)d_in[7];
    const float* bu = (const float*)d_in[8];
    float* out = (float*)d_out;

    float *pP, *pGiou, *pGf, *ph, *phs, *pxr, *pWx, *pWh, *pb;
    cudaGetSymbolAddress((void**)&pP,    g_P);
    cudaGetSymbolAddress((void**)&pGiou, g_Giou);
    cudaGetSymbolAddress((void**)&pGf,   g_Gf);
    cudaGetSymbolAddress((void**)&ph,    g_h);
    cudaGetSymbolAddress((void**)&phs,   g_hs);
    cudaGetSymbolAddress((void**)&pxr,   g_xr);
    cudaGetSymbolAddress((void**)&pWx,   g_Wx);
    cudaGetSymbolAddress((void**)&pWh,   g_Wh);
    cudaGetSymbolAddress((void**)&pb,    g_b);

    const int SMEM_GEMM = 4 * BUF * 4;   // 73728 B
    cudaFuncSetAttribute(gemm_cp,
                         cudaFuncAttributeMaxDynamicSharedMemorySize, SMEM_GEMM);
    cudaFuncSetAttribute(small_levels,
                         cudaFuncAttributeMaxDynamicSharedMemorySize, SMEM_GEMM);

    pack_weights<<<(G4 * DD + 255) / 256, 256>>>(Wi, bi, Wf, bf, Wo, bo, Wu, bu);
    round_x<<<(N_NODES * (DD / 4) + 255) / 256, 256>>>(x, pxr, N_NODES * (DD / 4));

    // P iou-part for ALL nodes: M=32767, N=1536, ldC=2048
    {
        dim3 grid(1536 / 128, (N_NODES + 127) / 128);
        gemm_cp<<<grid, 256, SMEM_GEMM>>>(pxr, pWx, pP, N_NODES, G4, pb);
    }
    // P f-part for INTERNAL nodes only: M=16383, N=512 at col offset 1536
    {
        int Mint = (1 << (DEPTH - 1)) - 1;   // 16383
        dim3 grid(512 / 128, (Mint + 127) / 128);
        gemm_cp<<<grid, 256, SMEM_GEMM>>>(pxr, pWx + (size_t)1536 * DD, pP + 1536,
                                          Mint, G4, pb + 1536);
    }

    // leaves (+ pair-sum for level 13)
    leaf_kernel<<<(1 << (DEPTH - 1)) * 128 / 256, 256>>>();

    // big internal levels 13..10
    for (int lvl = DEPTH - 2; lvl >= 10; lvl--) {
        int cnt = 1 << lvl;
        int start = cnt - 1;
        int cs = 2 * cnt - 1;
        {
            dim3 grid(1536 / 128, cnt / 128);
            gemm_cp<<<grid, 256, SMEM_GEMM>>>(phs, pWh, pGiou, cnt, 1536, nullptr);
        }
        {
            dim3 grid(512 / 128, 2 * cnt / 128);
            gemm_cp<<<grid, 256, SMEM_GEMM>>>(ph + (size_t)cs * HH,
                                              pWh + (size_t)(3 * HH) * DD,
                                              pGf, 2 * cnt, 512, nullptr);
        }
        combine_big<<<cnt * 128 / 256, 256>>>(start, cnt, cs);
    }

    // small levels 9..0 in one persistent launch
    small_levels<<<NCTA_PERS, 256, SMEM_GEMM>>>();

    write_out<<<(2 * HH + 255) / 256, 256>>>(out, out_size);
}

// round 8
// speedup vs baseline: 2.4491x; 1.0423x over previous
#include <cuda_runtime.h>
#include <cstdint>
#include <stdint.h>

#define DEPTH 15
#define N_NODES ((1 << DEPTH) - 1)   // 32767
#define DD 512
#define HH 512
#define G4 2048                      // gate cols packed [i | o | u | f]
#define SM_STRIDE 36
#define BUF (128 * SM_STRIDE)        // floats per A-or-W slab
#define NCTA_PERS 128

// ---------------- scratch ----------------
__device__ float g_P[(size_t)N_NODES * G4];
__device__ float g_Giou[(size_t)8192 * 1536];
__device__ float g_Gf[(size_t)16384 * HH];
__device__ float g_h[(size_t)N_NODES * HH];     // tf32-rounded h
__device__ float g_c[(size_t)N_NODES * HH];     // full-precision c
__device__ float g_hs[(size_t)8192 * HH];       // pair-summed h (rounded)
__device__ float g_xr[(size_t)N_NODES * DD];    // tf32-rounded x
__device__ float g_h0[HH];                      // full-precision h of node 0
__device__ float g_Wx[(size_t)G4 * DD];
__device__ float g_Wh[(size_t)G4 * HH];
__device__ float g_b[G4];
__device__ unsigned int g_bar_cnt;              // zero-init; self-resetting
__device__ unsigned int g_bar_rel;              // monotonic

// ---------------- helpers ----------------
__device__ __forceinline__ float tanh_fast(float x) {
    float y;
    asm("tanh.approx.f32 %0, %1;" : "=f"(y) : "f"(x));
    return y;
}
__device__ __forceinline__ float sig_fast(float x) {
    return 0.5f * tanh_fast(0.5f * x) + 0.5f;
}
__device__ __forceinline__ float to_tf32(float x) {
    unsigned int r;
    asm("cvt.rna.tf32.f32 %0, %1;" : "=r"(r) : "f"(x));
    return __uint_as_float(r);
}

// ---------------- pack weights [i|o|u|f] ----------------
__global__ void pack_weights(const float* __restrict__ Wi, const float* __restrict__ bi,
                             const float* __restrict__ Wf, const float* __restrict__ bf,
                             const float* __restrict__ Wo, const float* __restrict__ bo,
                             const float* __restrict__ Wu, const float* __restrict__ bu) {
    int idx = blockIdx.x * blockDim.x + threadIdx.x;
    if (idx < G4 * DD) {
        int row = idx >> 9;
        int col = idx & 511;
        int r = row & 511;
        int g = row >> 9;          // 0=i,1=o,2=u,3=f
        const float* W = (g == 0) ? Wi : (g == 1) ? Wo : (g == 2) ? Wu : Wf;
        const float* src = W + (size_t)r * (DD + HH);
        g_Wx[idx] = to_tf32(src[col]);
        g_Wh[idx] = to_tf32(src[DD + col]);
    }
    if (idx < G4) {
        int g = idx >> 9, r = idx & 511;
        const float* b = (g == 0) ? bi : (g == 1) ? bo : (g == 2) ? bu : bf;
        g_b[idx] = b[r];
    }
}

// ---------------- round x to tf32 ----------------
__global__ void round_x(const float* __restrict__ x, float* __restrict__ xr, int n4) {
    int idx = blockIdx.x * blockDim.x + threadIdx.x;
    if (idx >= n4) return;
    float4 v = *(const float4*)(x + (size_t)idx * 4);
    v.x = to_tf32(v.x); v.y = to_tf32(v.y); v.z = to_tf32(v.z); v.w = to_tf32(v.w);
    *(float4*)(xr + (size_t)idx * 4) = v;
}

// ---------------- cp.async tf32 GEMM tile, 3-stage, 1 sync/stage ----------------
// C[bm:bm+128, bn:bn+128] = A(M x 512) @ W(rows x 512)^T, row stride ldC, opt bias
__device__ __forceinline__ void gemm_tile(const float* __restrict__ A,
                                          const float* __restrict__ W,
                                          float* __restrict__ C,
                                          int M, int ldC,
                                          const float* __restrict__ bias,
                                          int bm, int bn, float* smem) {
    const int tid = threadIdx.x;
    const int lane = tid & 31;
    const int wid = tid >> 5;
    const int wm = (wid >> 2) << 6;   // 0 / 64
    const int wn = (wid & 3) << 5;    // 0 / 32 / 64 / 96
    const int g = lane >> 2;
    const int tig = lane & 3;
    const int c_row = tid >> 3;
    const int c_kq = (tid & 7) << 2;

    float acc[4][4][4];
#pragma unroll
    for (int mt = 0; mt < 4; mt++)
#pragma unroll
        for (int nt = 0; nt < 4; nt++)
#pragma unroll
            for (int r = 0; r < 4; r++) acc[mt][nt][r] = 0.f;

    auto issue = [&](int buf, int K0) {
        unsigned int sb = (unsigned int)__cvta_generic_to_shared(smem + buf * 2 * BUF);
#pragma unroll
        for (int i = 0; i < 4; i++) {
            int row = c_row + i * 32;
            int gr = bm + row;
            int zf = (gr < M) ? 16 : 0;
            const float* src = A + (size_t)(zf ? gr : 0) * DD + K0 + c_kq;
            asm volatile("cp.async.cg.shared.global [%0], [%1], 16, %2;"
                         :: "r"(sb + (unsigned)(row * SM_STRIDE + c_kq) * 4),
                            "l"(src), "r"(zf));
        }
        unsigned int sbw = sb + BUF * 4;
#pragma unroll
        for (int i = 0; i < 4; i++) {
            int row = c_row + i * 32;
            const float* src = W + (size_t)(bn + row) * DD + K0 + c_kq;
            asm volatile("cp.async.cg.shared.global [%0], [%1], 16;"
                         :: "r"(sbw + (unsigned)(row * SM_STRIDE + c_kq) * 4),
                            "l"(src));
        }
        asm volatile("cp.async.commit_group;");
    };

    issue(0, 0);
    issue(1, 32);
    int bfill = 2;   // next buffer to fill
    int bread = 0;   // buffer to compute from

    for (int s = 0; s < 16; s++) {
        if (s < 15) asm volatile("cp.async.wait_group 1;");
        else        asm volatile("cp.async.wait_group 0;");
        __syncthreads();
        if (s + 2 < 16) {
            issue(bfill, (s + 2) * 32);
            if (++bfill == 3) bfill = 0;
        }

        const float* As = smem + bread * 2 * BUF;
        const float* Ws = As + BUF;
        if (++bread == 3) bread = 0;
#pragma unroll
        for (int ks = 0; ks < 4; ks++) {
            const int kk = ks << 3;
            unsigned int a[4][4];
#pragma unroll
            for (int mt = 0; mt < 4; mt++) {
                int m = wm + (mt << 4) + g;
                a[mt][0] = __float_as_uint(As[m * SM_STRIDE + kk + tig]);
                a[mt][1] = __float_as_uint(As[(m + 8) * SM_STRIDE + kk + tig]);
                a[mt][2] = __float_as_uint(As[m * SM_STRIDE + kk + tig + 4]);
                a[mt][3] = __float_as_uint(As[(m + 8) * SM_STRIDE + kk + tig + 4]);
            }
            unsigned int b[4][2];
#pragma unroll
            for (int nt = 0; nt < 4; nt++) {
                int n = wn + (nt << 3) + g;
                b[nt][0] = __float_as_uint(Ws[n * SM_STRIDE + kk + tig]);
                b[nt][1] = __float_as_uint(Ws[n * SM_STRIDE + kk + tig + 4]);
            }
#pragma unroll
            for (int mt = 0; mt < 4; mt++)
#pragma unroll
                for (int nt = 0; nt < 4; nt++) {
                    float* c = acc[mt][nt];
                    asm volatile(
                        "mma.sync.aligned.m16n8k8.row.col.f32.tf32.tf32.f32 "
                        "{%0,%1,%2,%3}, {%4,%5,%6,%7}, {%8,%9}, {%0,%1,%2,%3};"
                        : "+f"(c[0]), "+f"(c[1]), "+f"(c[2]), "+f"(c[3])
                        : "r"(a[mt][0]), "r"(a[mt][1]), "r"(a[mt][2]), "r"(a[mt][3]),
                          "r"(b[nt][0]), "r"(b[nt][1]));
                }
        }
    }
    __syncthreads();   // protect smem before epilogue / next use

#pragma unroll
    for (int mt = 0; mt < 4; mt++) {
        int row0 = bm + wm + (mt << 4) + g;
#pragma unroll
        for (int nt = 0; nt < 4; nt++) {
            int col = bn + wn + (nt << 3) + (tig << 1);
            float b0 = 0.f, b1 = 0.f;
            if (bias) { b0 = bias[col]; b1 = bias[col + 1]; }
            if (row0 < M) {
                C[(size_t)row0 * ldC + col]     = acc[mt][nt][0] + b0;
                C[(size_t)row0 * ldC + col + 1] = acc[mt][nt][1] + b1;
            }
            if (row0 + 8 < M) {
                C[(size_t)(row0 + 8) * ldC + col]     = acc[mt][nt][2] + b0;
                C[(size_t)(row0 + 8) * ldC + col + 1] = acc[mt][nt][3] + b1;
            }
        }
    }
}

// ---------------- merged big-P GEMM: iou (all nodes) + f (internal) ----------
#define TILES_P_IOU (12 * 256)   // 1536/128 cols x ceil(32767/128)=256 rows
__global__ __launch_bounds__(256, 2) void big_P_gemm() {
    extern __shared__ float smem[];
    int t = blockIdx.x;
    if (t < TILES_P_IOU) {
        int by = t / 12, bx = t % 12;
        gemm_tile(g_xr, g_Wx, g_P, N_NODES, G4, g_b, by * 128, bx * 128, smem);
    } else {
        int t2 = t - TILES_P_IOU;
        int by = t2 >> 2, bx = t2 & 3;   // 4 cols x 128 rows
        gemm_tile(g_xr, g_Wx + (size_t)1536 * DD, g_P + 1536,
                  (1 << (DEPTH - 1)) - 1, G4, g_b + 1536, by * 128, bx * 128, smem);
    }
}

// ---------------- merged level GEMMs: iou on h-sums + f on raw children ------
__global__ __launch_bounds__(256, 2) void level_gemms(int cnt) {
    extern __shared__ float smem[];
    int cs = 2 * cnt - 1;
    int tiles_i = (cnt >> 7) * 12;       // cnt >= 1024 here
    int t = blockIdx.x;
    if (t < tiles_i) {
        int by = t / 12, bx = t % 12;
        gemm_tile(g_hs, g_Wh, g_Giou, cnt, 1536, nullptr, by * 128, bx * 128, smem);
    } else {
        int t2 = t - tiles_i;
        int by = t2 >> 2, bx = t2 & 3;
        gemm_tile(g_h + (size_t)cs * HH, g_Wh + (size_t)(3 * HH) * DD,
                  g_Gf, 2 * cnt, 512, nullptr, by * 128, bx * 128, smem);
    }
}

// ---------------- combine unit (fused pair-sum) ----------------
__device__ __forceinline__ void combine_unit(int u, int U, int start, int cs,
                                             bool write_hs, float4* sh) {
    float4 h4 = make_float4(0.f, 0.f, 0.f, 0.f);
    int b = u >> 7, j4 = (u & 127) << 2;
    if (u < U) {
        size_t n = (size_t)(start + b);
        const float* Pp = g_P + n * G4;
        const float* Gi = g_Giou + (size_t)b * 1536;
        float4 pi = *(const float4*)(Pp + j4);
        float4 po = *(const float4*)(Pp + HH + j4);
        float4 pu = *(const float4*)(Pp + 2 * HH + j4);
        float4 pf = *(const float4*)(Pp + 3 * HH + j4);
        float4 gi = *(const float4*)(Gi + j4);
        float4 go = *(const float4*)(Gi + HH + j4);
        float4 gu = *(const float4*)(Gi + 2 * HH + j4);
        float4 gfl = *(const float4*)(g_Gf + (size_t)(2 * b) * HH + j4);
        float4 gfr = *(const float4*)(g_Gf + (size_t)(2 * b + 1) * HH + j4);
        float4 cl = *(const float4*)(g_c + (size_t)(cs + 2 * b) * HH + j4);
        float4 cr = *(const float4*)(g_c + (size_t)(cs + 2 * b + 1) * HH + j4);
        float4 c4, hfull;
#define COMB(X)                                                  \
        {                                                        \
            float i_ = sig_fast(pi.X + gi.X);                    \
            float o_ = sig_fast(po.X + go.X);                    \
            float u_ = tanh_fast(pu.X + gu.X);                   \
            float fl_ = sig_fast(pf.X + gfl.X);                  \
            float fr_ = sig_fast(pf.X + gfr.X);                  \
            c4.X = i_ * u_ + fl_ * cl.X + fr_ * cr.X;            \
            hfull.X = o_ * tanh_fast(c4.X);                      \
            h4.X = to_tf32(hfull.X);                             \
        }
        COMB(x) COMB(y) COMB(z) COMB(w)
#undef COMB
        *(float4*)(g_c + n * HH + j4) = c4;
        *(float4*)(g_h + n * HH + j4) = h4;
        if (n == 0) *(float4*)(g_h0 + j4) = hfull;
    }
    sh[threadIdx.x] = h4;
    __syncthreads();
    if (write_hs && threadIdx.x < 128 && u < U) {
        float4 o = sh[threadIdx.x + 128];
        float4 s;
        s.x = to_tf32(h4.x + o.x); s.y = to_tf32(h4.y + o.y);
        s.z = to_tf32(h4.z + o.z); s.w = to_tf32(h4.w + o.w);
        *(float4*)(g_hs + (size_t)(b >> 1) * HH + j4) = s;
    }
    __syncthreads();
}

// ---------------- big-level combine ----------------
__global__ void combine_big(int start, int cnt, int cs) {
    __shared__ float4 sh[256];
    int u = blockIdx.x * 256 + threadIdx.x;
    combine_unit(u, cnt << 7, start, cs, true, sh);
}

// ---------------- leaf level (+ fused pair-sum) ----------------
__global__ void leaf_kernel() {
    __shared__ float4 sh[256];
    int u = blockIdx.x * 256 + threadIdx.x;
    int b = u >> 7, j4 = (u & 127) << 2;
    size_t n = (size_t)((1 << (DEPTH - 1)) - 1 + b);
    const float* Pp = g_P + n * G4;
    float4 pi = *(const float4*)(Pp + j4);
    float4 po = *(const float4*)(Pp + HH + j4);
    float4 pu = *(const float4*)(Pp + 2 * HH + j4);
    float4 c4, h4;
#define LEAF1(X)                                             \
    {                                                        \
        float i_ = sig_fast(pi.X), o_ = sig_fast(po.X);      \
        float u_ = tanh_fast(pu.X);                          \
        c4.X = i_ * u_;                                      \
        h4.X = to_tf32(o_ * tanh_fast(c4.X));                \
    }
    LEAF1(x) LEAF1(y) LEAF1(z) LEAF1(w)
#undef LEAF1
    *(float4*)(g_c + n * HH + j4) = c4;
    *(float4*)(g_h + n * HH + j4) = h4;
    sh[threadIdx.x] = h4;
    __syncthreads();
    if (threadIdx.x < 128) {
        float4 o = sh[threadIdx.x + 128];
        float4 s;
        s.x = to_tf32(h4.x + o.x); s.y = to_tf32(h4.y + o.y);
        s.z = to_tf32(h4.z + o.z); s.w = to_tf32(h4.w + o.w);
        *(float4*)(g_hs + (size_t)(b >> 1) * HH + j4) = s;
    }
}

// ---------------- software grid barrier (replay-safe) ----------------
__device__ __forceinline__ void grid_sync(unsigned int gen, unsigned int rel_base) {
    __syncthreads();
    if (threadIdx.x == 0) {
        __threadfence();
        unsigned int a = atomicAdd(&g_bar_cnt, 1);
        if (a == NCTA_PERS - 1) {
            g_bar_cnt = 0;
            __threadfence();
            atomicAdd(&g_bar_rel, 1);
        } else {
            while (*(volatile unsigned int*)&g_bar_rel - rel_base < gen) { }
        }
        __threadfence();
    }
    __syncthreads();
}

// ---------------- persistent kernel: levels 9..0 ----------------
__global__ __launch_bounds__(256) void small_levels() {
    extern __shared__ float smem[];
    unsigned int rel_base = *(volatile unsigned int*)&g_bar_rel;
    unsigned int gen = 0;
    for (int lvl = 9; lvl >= 0; lvl--) {
        int cnt = 1 << lvl;
        int start = cnt - 1;
        int cs = 2 * cnt - 1;
        int tiles_i = ((cnt + 127) >> 7) * 12;
        int tiles_f = ((2 * cnt + 127) >> 7) * 4;
        int tot = tiles_i + tiles_f;
        for (int t = blockIdx.x; t < tot; t += NCTA_PERS) {
            if (t < tiles_i) {
                int by = t / 12, bx = t % 12;
                gemm_tile(g_hs, g_Wh, g_Giou, cnt, 1536, nullptr,
                          by * 128, bx * 128, smem);
            } else {
                int t2 = t - tiles_i;
                int by = t2 >> 2, bx = t2 & 3;
                gemm_tile(g_h + (size_t)cs * HH, g_Wh + (size_t)(3 * HH) * DD,
                          g_Gf, 2 * cnt, 512, nullptr, by * 128, bx * 128, smem);
            }
        }
        gen++; grid_sync(gen, rel_base);
        int U = cnt << 7;
        for (int base = blockIdx.x * 256; base < U; base += NCTA_PERS * 256) {
            combine_unit(base + (int)threadIdx.x, U, start, cs, lvl > 0,
                         (float4*)smem);
        }
        gen++; grid_sync(gen, rel_base);
    }
}

// ---------------- output: [h[0] | c[0]] ----------------
__global__ void write_out(float* __restrict__ out, int out_size) {
    int j = blockIdx.x * blockDim.x + threadIdx.x;
    if (j < HH && j < out_size) out[j] = g_h0[j];
    int j2 = j + HH;
    if (j < HH && j2 < out_size) out[j2] = g_c[j];
}

extern "C" void kernel_launch(void* const* d_in, const int* in_sizes, int n_in,
                              void* d_out, int out_size) {
    const float* x  = (const float*)d_in[0];
    const float* Wi = (const float*)d_in[1];
    const float* bi = (const float*)d_in[2];
    const float* Wf = (const float*)d_in[3];
    const float* bf = (const float*)d_in[4];
    const float* Wo = (const float*)d_in[5];
    const float* bo = (const float*)d_in[6];
    const float* Wu = (const float*)d_in[7];
    const float* bu = (const float*)d_in[8];
    float* out = (float*)d_out;

    float* pxr;
    cudaGetSymbolAddress((void**)&pxr, g_xr);

    const int SMEM_GEMM = 6 * BUF * 4;   // 110592 B (3 stages x 2 slabs)
    cudaFuncSetAttribute(big_P_gemm,
                         cudaFuncAttributeMaxDynamicSharedMemorySize, SMEM_GEMM);
    cudaFuncSetAttribute(level_gemms,
                         cudaFuncAttributeMaxDynamicSharedMemorySize, SMEM_GEMM);
    cudaFuncSetAttribute(small_levels,
                         cudaFuncAttributeMaxDynamicSharedMemorySize, SMEM_GEMM);

    pack_weights<<<(G4 * DD + 255) / 256, 256>>>(Wi, bi, Wf, bf, Wo, bo, Wu, bu);
    round_x<<<(N_NODES * (DD / 4) + 255) / 256, 256>>>(x, pxr, N_NODES * (DD / 4));

    // P: iou for all nodes + f for internal nodes, one launch
    {
        int grid = TILES_P_IOU + 4 * 128;   // 3072 + 512
        big_P_gemm<<<grid, 256, SMEM_GEMM>>>();
    }

    // leaves (+ pair-sum for level 13)
    leaf_kernel<<<(1 << (DEPTH - 1)) * 128 / 256, 256>>>();

    // big internal levels 13..10
    for (int lvl = DEPTH - 2; lvl >= 10; lvl--) {
        int cnt = 1 << lvl;
        int start = cnt - 1;
        int cs = 2 * cnt - 1;
        int grid = (cnt >> 7) * 12 + ((2 * cnt) >> 7) * 4;
        level_gemms<<<grid, 256, SMEM_GEMM>>>(cnt);
        combine_big<<<cnt * 128 / 256, 256>>>(start, cnt, cs);
    }

    // small levels 9..0 in one persistent launch
    small_levels<<<NCTA_PERS, 256, SMEM_GEMM>>>();

    write_out<<<(2 * HH + 255) / 256, 256>>>(out, out_size);
}

// round 9
// speedup vs baseline: 2.8914x; 1.1806x over previous
#include <cuda_runtime.h>
#include <cuda_fp16.h>
#include <cstdint>
#include <stdint.h>

#define DEPTH 15
#define N_NODES ((1 << DEPTH) - 1)   // 32767
#define DD 512
#define HH 512
#define G4 2048                      // gate cols packed [i | o | u | f]
#define AST 40                       // halfs per padded smem row (80 B)
#define SLABB (128 * AST * 2)        // bytes per slab (10240)
#define NCTA_PERS 128

// ---------------- scratch ----------------
__device__ float g_P[(size_t)N_NODES * G4];
__device__ float g_Giou[(size_t)8192 * 1536];
__device__ float g_Gf[(size_t)16384 * HH];
__device__ __half g_h[(size_t)N_NODES * HH];    // fp16 h (GEMM input)
__device__ float g_c[(size_t)N_NODES * HH];     // full-precision c
__device__ __half g_hs[(size_t)8192 * HH];      // pair-summed h (fp16)
__device__ __half g_xr[(size_t)N_NODES * DD];   // fp16 x
__device__ float g_h0[HH];                      // full-precision h of node 0
__device__ __half g_Wx[(size_t)G4 * DD];
__device__ __half g_Wh[(size_t)G4 * HH];
__device__ float g_b[G4];
__device__ unsigned int g_bar_cnt;
__device__ unsigned int g_bar_rel;

// ---------------- helpers ----------------
__device__ __forceinline__ float tanh_fast(float x) {
    float y;
    asm("tanh.approx.f32 %0, %1;" : "=f"(y) : "f"(x));
    return y;
}
__device__ __forceinline__ float sig_fast(float x) {
    return 0.5f * tanh_fast(0.5f * x) + 0.5f;
}

// ---------------- pack weights [i|o|u|f] ----------------
__global__ void pack_weights(const float* __restrict__ Wi, const float* __restrict__ bi,
                             const float* __restrict__ Wf, const float* __restrict__ bf,
                             const float* __restrict__ Wo, const float* __restrict__ bo,
                             const float* __restrict__ Wu, const float* __restrict__ bu) {
    int idx = blockIdx.x * blockDim.x + threadIdx.x;
    if (idx < G4 * DD) {
        int row = idx >> 9;
        int col = idx & 511;
        int r = row & 511;
        int g = row >> 9;          // 0=i,1=o,2=u,3=f
        const float* W = (g == 0) ? Wi : (g == 1) ? Wo : (g == 2) ? Wu : Wf;
        const float* src = W + (size_t)r * (DD + HH);
        g_Wx[idx] = __float2half_rn(src[col]);
        g_Wh[idx] = __float2half_rn(src[DD + col]);
    }
    if (idx < G4) {
        int g = idx >> 9, r = idx & 511;
        const float* b = (g == 0) ? bi : (g == 1) ? bo : (g == 2) ? bu : bf;
        g_b[idx] = b[r];
    }
}

// ---------------- convert x to fp16 ----------------
__global__ void round_x(const float* __restrict__ x, __half* __restrict__ xr, int n4) {
    int idx = blockIdx.x * blockDim.x + threadIdx.x;
    if (idx >= n4) return;
    float4 v = *(const float4*)(x + (size_t)idx * 4);
    __half2* dst = (__half2*)(xr + (size_t)idx * 4);
    dst[0] = __floats2half2_rn(v.x, v.y);
    dst[1] = __floats2half2_rn(v.z, v.w);
}

// ---------------- fp16 GEMM tile: 3-stage cp.async + ldmatrix + m16n8k16 -----
// C[bm:bm+128, bn:bn+128] = A(M x 512) @ W(rows x 512)^T, fp32 out, opt bias
__device__ __forceinline__ void gemm_tile(const __half* __restrict__ A,
                                          const __half* __restrict__ W,
                                          float* __restrict__ C,
                                          int M, int ldC,
                                          const float* __restrict__ bias,
                                          int bm, int bn, __half* smem) {
    const int tid = threadIdx.x;
    const int lane = tid & 31;
    const int wid = tid >> 5;
    const int wm = (wid >> 2) << 6;   // 0 / 64
    const int wn = (wid & 3) << 5;    // 0 / 32 / 64 / 96
    const int g = lane >> 2;
    const int tig = lane & 3;

    const unsigned int smem_u = (unsigned int)__cvta_generic_to_shared(smem);

    // copy mapping: 512 x 16B chunks per slab, 2 per thread per slab
    const int c_rowA = tid & 127;             // row for id=tid (q = tid>>7)
    // ldmatrix lane bases (bytes within slab, without ks term)
    int a_base[4];
#pragma unroll
    for (int mt = 0; mt < 4; mt++)
        a_base[mt] = (wm + mt * 16 + (lane & 15)) * 80 + ((lane >> 4) & 1) * 16;
    int b_base[2];
#pragma unroll
    for (int ntp = 0; ntp < 2; ntp++)
        b_base[ntp] = (wn + ntp * 16 + ((lane >> 4) << 3) + (lane & 7)) * 80 +
                      ((lane >> 3) & 1) * 16;

    float acc[4][4][4];
#pragma unroll
    for (int mt = 0; mt < 4; mt++)
#pragma unroll
        for (int nt = 0; nt < 4; nt++)
#pragma unroll
            for (int r = 0; r < 4; r++) acc[mt][nt][r] = 0.f;

    auto issue = [&](int buf, int K0) {   // K0 in halfs
        unsigned int sb = smem_u + buf * 2 * SLABB;
#pragma unroll
        for (int i = 0; i < 2; i++) {
            int id = tid + i * 256;
            int row = id & 127;
            int q = id >> 7;
            int gr = bm + row;
            int zf = (gr < M) ? 16 : 0;
            const __half* src = A + (size_t)(zf ? gr : 0) * DD + K0 + q * 8;
            asm volatile("cp.async.cg.shared.global [%0], [%1], 16, %2;"
                         :: "r"(sb + (unsigned)(row * 80 + q * 16)),
                            "l"(src), "r"(zf));
        }
        unsigned int sbw = sb + SLABB;
#pragma unroll
        for (int i = 0; i < 2; i++) {
            int id = tid + i * 256;
            int row = id & 127;
            int q = id >> 7;
            const __half* src = W + (size_t)(bn + row) * DD + K0 + q * 8;
            asm volatile("cp.async.cg.shared.global [%0], [%1], 16;"
                         :: "r"(sbw + (unsigned)(row * 80 + q * 16)),
                            "l"(src));
        }
        asm volatile("cp.async.commit_group;");
    };

    issue(0, 0);
    issue(1, 32);
    int bfill = 2, bread = 0;

    for (int s = 0; s < 16; s++) {
        if (s < 15) asm volatile("cp.async.wait_group 1;");
        else        asm volatile("cp.async.wait_group 0;");
        __syncthreads();
        if (s + 2 < 16) {
            issue(bfill, (s + 2) * 32);
            if (++bfill == 3) bfill = 0;
        }

        unsigned int As = smem_u + bread * 2 * SLABB;
        unsigned int Ws = As + SLABB;
        if (++bread == 3) bread = 0;

#pragma unroll
        for (int ks = 0; ks < 2; ks++) {
            const int kb = ks * 32;   // byte offset of this K=16 chunk
            unsigned int a[4][4];
#pragma unroll
            for (int mt = 0; mt < 4; mt++) {
                asm volatile("ldmatrix.sync.aligned.m8n8.x4.shared.b16 "
                             "{%0,%1,%2,%3}, [%4];"
                             : "=r"(a[mt][0]), "=r"(a[mt][1]),
                               "=r"(a[mt][2]), "=r"(a[mt][3])
                             : "r"(As + (unsigned)(a_base[mt] + kb)));
            }
            unsigned int b[2][4];
#pragma unroll
            for (int ntp = 0; ntp < 2; ntp++) {
                asm volatile("ldmatrix.sync.aligned.m8n8.x4.shared.b16 "
                             "{%0,%1,%2,%3}, [%4];"
                             : "=r"(b[ntp][0]), "=r"(b[ntp][1]),
                               "=r"(b[ntp][2]), "=r"(b[ntp][3])
                             : "r"(Ws + (unsigned)(b_base[ntp] + kb)));
            }
#pragma unroll
            for (int mt = 0; mt < 4; mt++)
#pragma unroll
                for (int nt = 0; nt < 4; nt++) {
                    float* c = acc[mt][nt];
                    unsigned int b0 = b[nt >> 1][(nt & 1) * 2];
                    unsigned int b1 = b[nt >> 1][(nt & 1) * 2 + 1];
                    asm volatile(
                        "mma.sync.aligned.m16n8k16.row.col.f32.f16.f16.f32 "
                        "{%0,%1,%2,%3}, {%4,%5,%6,%7}, {%8,%9}, {%0,%1,%2,%3};"
                        : "+f"(c[0]), "+f"(c[1]), "+f"(c[2]), "+f"(c[3])
                        : "r"(a[mt][0]), "r"(a[mt][1]), "r"(a[mt][2]), "r"(a[mt][3]),
                          "r"(b0), "r"(b1));
                }
        }
    }
    __syncthreads();   // protect smem before next tile / reuse

#pragma unroll
    for (int mt = 0; mt < 4; mt++) {
        int row0 = bm + wm + (mt << 4) + g;
#pragma unroll
        for (int nt = 0; nt < 4; nt++) {
            int col = bn + wn + (nt << 3) + (tig << 1);
            float b0 = 0.f, b1 = 0.f;
            if (bias) { b0 = bias[col]; b1 = bias[col + 1]; }
            if (row0 < M) {
                C[(size_t)row0 * ldC + col]     = acc[mt][nt][0] + b0;
                C[(size_t)row0 * ldC + col + 1] = acc[mt][nt][1] + b1;
            }
            if (row0 + 8 < M) {
                C[(size_t)(row0 + 8) * ldC + col]     = acc[mt][nt][2] + b0;
                C[(size_t)(row0 + 8) * ldC + col + 1] = acc[mt][nt][3] + b1;
            }
        }
    }
}

// ---------------- merged big-P GEMM: iou (all nodes) + f (internal) ----------
#define TILES_P_IOU (12 * 256)
__global__ __launch_bounds__(256, 2) void big_P_gemm() {
    extern __shared__ __half smem[];
    int t = blockIdx.x;
    if (t < TILES_P_IOU) {
        int by = t / 12, bx = t % 12;
        gemm_tile(g_xr, g_Wx, g_P, N_NODES, G4, g_b, by * 128, bx * 128, smem);
    } else {
        int t2 = t - TILES_P_IOU;
        int by = t2 >> 2, bx = t2 & 3;
        gemm_tile(g_xr, g_Wx + (size_t)1536 * DD, g_P + 1536,
                  (1 << (DEPTH - 1)) - 1, G4, g_b + 1536, by * 128, bx * 128, smem);
    }
}

// ---------------- merged level GEMMs ----------------
__global__ __launch_bounds__(256, 2) void level_gemms(int cnt) {
    extern __shared__ __half smem[];
    int cs = 2 * cnt - 1;
    int tiles_i = (cnt >> 7) * 12;
    int t = blockIdx.x;
    if (t < tiles_i) {
        int by = t / 12, bx = t % 12;
        gemm_tile(g_hs, g_Wh, g_Giou, cnt, 1536, nullptr, by * 128, bx * 128, smem);
    } else {
        int t2 = t - tiles_i;
        int by = t2 >> 2, bx = t2 & 3;
        gemm_tile(g_h + (size_t)cs * HH, g_Wh + (size_t)(3 * HH) * DD,
                  g_Gf, 2 * cnt, 512, nullptr, by * 128, bx * 128, smem);
    }
}

// ---------------- combine unit (fused pair-sum) ----------------
__device__ __forceinline__ void combine_unit(int u, int U, int start, int cs,
                                             bool write_hs, float4* sh) {
    float4 hfull = make_float4(0.f, 0.f, 0.f, 0.f);
    int b = u >> 7, j4 = (u & 127) << 2;
    if (u < U) {
        size_t n = (size_t)(start + b);
        const float* Pp = g_P + n * G4;
        const float* Gi = g_Giou + (size_t)b * 1536;
        float4 pi = *(const float4*)(Pp + j4);
        float4 po = *(const float4*)(Pp + HH + j4);
        float4 pu = *(const float4*)(Pp + 2 * HH + j4);
        float4 pf = *(const float4*)(Pp + 3 * HH + j4);
        float4 gi = *(const float4*)(Gi + j4);
        float4 go = *(const float4*)(Gi + HH + j4);
        float4 gu = *(const float4*)(Gi + 2 * HH + j4);
        float4 gfl = *(const float4*)(g_Gf + (size_t)(2 * b) * HH + j4);
        float4 gfr = *(const float4*)(g_Gf + (size_t)(2 * b + 1) * HH + j4);
        float4 cl = *(const float4*)(g_c + (size_t)(cs + 2 * b) * HH + j4);
        float4 cr = *(const float4*)(g_c + (size_t)(cs + 2 * b + 1) * HH + j4);
        float4 c4;
#define COMB(X)                                                  \
        {                                                        \
            float i_ = sig_fast(pi.X + gi.X);                    \
            float o_ = sig_fast(po.X + go.X);                    \
            float u_ = tanh_fast(pu.X + gu.X);                   \
            float fl_ = sig_fast(pf.X + gfl.X);                  \
            float fr_ = sig_fast(pf.X + gfr.X);                  \
            c4.X = i_ * u_ + fl_ * cl.X + fr_ * cr.X;            \
            hfull.X = o_ * tanh_fast(c4.X);                      \
        }
        COMB(x) COMB(y) COMB(z) COMB(w)
#undef COMB
        *(float4*)(g_c + n * HH + j4) = c4;
        __half2* hd = (__half2*)(g_h + n * HH + j4);
        hd[0] = __floats2half2_rn(hfull.x, hfull.y);
        hd[1] = __floats2half2_rn(hfull.z, hfull.w);
        if (n == 0) *(float4*)(g_h0 + j4) = hfull;
    }
    sh[threadIdx.x] = hfull;
    __syncthreads();
    if (write_hs && threadIdx.x < 128 && u < U) {
        float4 o = sh[threadIdx.x + 128];
        __half2* hd = (__half2*)(g_hs + (size_t)(b >> 1) * HH + j4);
        hd[0] = __floats2half2_rn(hfull.x + o.x, hfull.y + o.y);
        hd[1] = __floats2half2_rn(hfull.z + o.z, hfull.w + o.w);
    }
    __syncthreads();
}

// ---------------- big-level combine ----------------
__global__ void combine_big(int start, int cnt, int cs) {
    __shared__ float4 sh[256];
    int u = blockIdx.x * 256 + threadIdx.x;
    combine_unit(u, cnt << 7, start, cs, true, sh);
}

// ---------------- leaf level (+ fused pair-sum) ----------------
__global__ void leaf_kernel() {
    __shared__ float4 sh[256];
    int u = blockIdx.x * 256 + threadIdx.x;
    int b = u >> 7, j4 = (u & 127) << 2;
    size_t n = (size_t)((1 << (DEPTH - 1)) - 1 + b);
    const float* Pp = g_P + n * G4;
    float4 pi = *(const float4*)(Pp + j4);
    float4 po = *(const float4*)(Pp + HH + j4);
    float4 pu = *(const float4*)(Pp + 2 * HH + j4);
    float4 c4, hfull;
#define LEAF1(X)                                             \
    {                                                        \
        float i_ = sig_fast(pi.X), o_ = sig_fast(po.X);      \
        float u_ = tanh_fast(pu.X);                          \
        c4.X = i_ * u_;                                      \
        hfull.X = o_ * tanh_fast(c4.X);                      \
    }
    LEAF1(x) LEAF1(y) LEAF1(z) LEAF1(w)
#undef LEAF1
    *(float4*)(g_c + n * HH + j4) = c4;
    __half2* hd = (__half2*)(g_h + n * HH + j4);
    hd[0] = __floats2half2_rn(hfull.x, hfull.y);
    hd[1] = __floats2half2_rn(hfull.z, hfull.w);
    sh[threadIdx.x] = hfull;
    __syncthreads();
    if (threadIdx.x < 128) {
        float4 o = sh[threadIdx.x + 128];
        __half2* hs = (__half2*)(g_hs + (size_t)(b >> 1) * HH + j4);
        hs[0] = __floats2half2_rn(hfull.x + o.x, hfull.y + o.y);
        hs[1] = __floats2half2_rn(hfull.z + o.z, hfull.w + o.w);
    }
}

// ---------------- software grid barrier (replay-safe) ----------------
__device__ __forceinline__ void grid_sync(unsigned int gen, unsigned int rel_base) {
    __syncthreads();
    if (threadIdx.x == 0) {
        __threadfence();
        unsigned int a = atomicAdd(&g_bar_cnt, 1);
        if (a == NCTA_PERS - 1) {
            g_bar_cnt = 0;
            __threadfence();
            atomicAdd(&g_bar_rel, 1);
        } else {
            while (*(volatile unsigned int*)&g_bar_rel - rel_base < gen) { }
        }
        __threadfence();
    }
    __syncthreads();
}

// ---------------- persistent kernel: levels 9..0 ----------------
__global__ __launch_bounds__(256) void small_levels() {
    extern __shared__ __half smem[];
    unsigned int rel_base = *(volatile unsigned int*)&g_bar_rel;
    unsigned int gen = 0;
    for (int lvl = 9; lvl >= 0; lvl--) {
        int cnt = 1 << lvl;
        int start = cnt - 1;
        int cs = 2 * cnt - 1;
        int tiles_i = ((cnt + 127) >> 7) * 12;
        int tiles_f = ((2 * cnt + 127) >> 7) * 4;
        int tot = tiles_i + tiles_f;
        for (int t = blockIdx.x; t < tot; t += NCTA_PERS) {
            if (t < tiles_i) {
                int by = t / 12, bx = t % 12;
                gemm_tile(g_hs, g_Wh, g_Giou, cnt, 1536, nullptr,
                          by * 128, bx * 128, smem);
            } else {
                int t2 = t - tiles_i;
                int by = t2 >> 2, bx = t2 & 3;
                gemm_tile(g_h + (size_t)cs * HH, g_Wh + (size_t)(3 * HH) * DD,
                          g_Gf, 2 * cnt, 512, nullptr, by * 128, bx * 128, smem);
            }
        }
        gen++; grid_sync(gen, rel_base);
        int U = cnt << 7;
        for (int base = blockIdx.x * 256; base < U; base += NCTA_PERS * 256) {
            combine_unit(base + (int)threadIdx.x, U, start, cs, lvl > 0,
                         (float4*)smem);
        }
        gen++; grid_sync(gen, rel_base);
    }
}

// ---------------- output: [h[0] | c[0]] ----------------
__global__ void write_out(float* __restrict__ out, int out_size) {
    int j = blockIdx.x * blockDim.x + threadIdx.x;
    if (j < HH && j < out_size) out[j] = g_h0[j];
    int j2 = j + HH;
    if (j < HH && j2 < out_size) out[j2] = g_c[j];
}

extern "C" void kernel_launch(void* const* d_in, const int* in_sizes, int n_in,
                              void* d_out, int out_size) {
    const float* x  = (const float*)d_in[0];
    const float* Wi = (const float*)d_in[1];
    const float* bi = (const float*)d_in[2];
    const float* Wf = (const float*)d_in[3];
    const float* bf = (const float*)d_in[4];
    const float* Wo = (const float*)d_in[5];
    const float* bo = (const float*)d_in[6];
    const float* Wu = (const float*)d_in[7];
    const float* bu = (const float*)d_in[8];
    float* out = (float*)d_out;

    __half* pxr;
    cudaGetSymbolAddress((void**)&pxr, g_xr);

    const int SMEM_GEMM = 6 * SLABB;   // 61440 B (3 stages x 2 slabs)
    cudaFuncSetAttribute(big_P_gemm,
                         cudaFuncAttributeMaxDynamicSharedMemorySize, SMEM_GEMM);
    cudaFuncSetAttribute(level_gemms,
                         cudaFuncAttributeMaxDynamicSharedMemorySize, SMEM_GEMM);
    cudaFuncSetAttribute(small_levels,
                         cudaFuncAttributeMaxDynamicSharedMemorySize, SMEM_GEMM);

    pack_weights<<<(G4 * DD + 255) / 256, 256>>>(Wi, bi, Wf, bf, Wo, bo, Wu, bu);
    round_x<<<(N_NODES * (DD / 4) + 255) / 256, 256>>>(x, pxr, N_NODES * (DD / 4));

    // P: iou for all nodes + f for internal nodes, one launch
    {
        int grid = TILES_P_IOU + 4 * 128;
        big_P_gemm<<<grid, 256, SMEM_GEMM>>>();
    }

    // leaves (+ pair-sum for level 13)
    leaf_kernel<<<(1 << (DEPTH - 1)) * 128 / 256, 256>>>();

    // big internal levels 13..10
    for (int lvl = DEPTH - 2; lvl >= 10; lvl--) {
        int cnt = 1 << lvl;
        int start = cnt - 1;
        int cs = 2 * cnt - 1;
        int grid = (cnt >> 7) * 12 + ((2 * cnt) >> 7) * 4;
        level_gemms<<<grid, 256, SMEM_GEMM>>>(cnt);
        combine_big<<<cnt * 128 / 256, 256>>>(start, cnt, cs);
    }

    // small levels 9..0 in one persistent launch
    small_levels<<<NCTA_PERS, 256, SMEM_GEMM>>>();

    write_out<<<(2 * HH + 255) / 256, 256>>>(out, out_size);
}

// round 10
// speedup vs baseline: 3.1827x; 1.1007x over previous
#include <cuda_runtime.h>
#include <cuda_fp16.h>
#include <cstdint>
#include <stdint.h>

#define DEPTH 15
#define N_NODES ((1 << DEPTH) - 1)   // 32767
#define DD 512
#define HH 512
#define G4 2048                      // gate cols packed [i | o | u | f]
#define AST 40                       // halfs per padded smem row (80 B)
#define SLABB (128 * AST * 2)        // bytes per slab (10240)
#define NCTA_PERS 128

// ---------------- scratch ----------------
__device__ __half g_P[(size_t)N_NODES * G4];    // fp16 pre-activations
__device__ __half g_Giou[(size_t)8192 * 1536];  // fp16
__device__ __half g_Gf[(size_t)16384 * HH];     // fp16
__device__ __half g_h[(size_t)N_NODES * HH];    // fp16 h (GEMM input)
__device__ float g_c[(size_t)N_NODES * HH];     // full-precision c
__device__ __half g_hs[(size_t)8192 * HH];      // pair-summed h (fp16)
__device__ __half g_xr[(size_t)N_NODES * DD];   // fp16 x
__device__ float g_h0[HH];                      // full-precision h of node 0
__device__ __half g_Wx[(size_t)G4 * DD];
__device__ __half g_Wh[(size_t)G4 * HH];
__device__ float g_b[G4];
__device__ unsigned int g_bar_cnt;
__device__ unsigned int g_bar_rel;

// ---------------- helpers ----------------
__device__ __forceinline__ float tanh_fast(float x) {
    float y;
    asm("tanh.approx.f32 %0, %1;" : "=f"(y) : "f"(x));
    return y;
}
__device__ __forceinline__ float sig_fast(float x) {
    return 0.5f * tanh_fast(0.5f * x) + 0.5f;
}
__device__ __forceinline__ float4 ldh4(const __half* p) {
    __half2 a = *(const __half2*)p;
    __half2 b = *(const __half2*)(p + 2);
    float2 fa = __half22float2(a), fb = __half22float2(b);
    return make_float4(fa.x, fa.y, fb.x, fb.y);
}

// ---------------- pack weights [i|o|u|f] ----------------
__global__ void pack_weights(const float* __restrict__ Wi, const float* __restrict__ bi,
                             const float* __restrict__ Wf, const float* __restrict__ bf,
                             const float* __restrict__ Wo, const float* __restrict__ bo,
                             const float* __restrict__ Wu, const float* __restrict__ bu) {
    int idx = blockIdx.x * blockDim.x + threadIdx.x;
    if (idx < G4 * DD) {
        int row = idx >> 9;
        int col = idx & 511;
        int r = row & 511;
        int g = row >> 9;          // 0=i,1=o,2=u,3=f
        const float* W = (g == 0) ? Wi : (g == 1) ? Wo : (g == 2) ? Wu : Wf;
        const float* src = W + (size_t)r * (DD + HH);
        g_Wx[idx] = __float2half_rn(src[col]);
        g_Wh[idx] = __float2half_rn(src[DD + col]);
    }
    if (idx < G4) {
        int g = idx >> 9, r = idx & 511;
        const float* b = (g == 0) ? bi : (g == 1) ? bo : (g == 2) ? bu : bf;
        g_b[idx] = b[r];
    }
}

// ---------------- convert x to fp16 ----------------
__global__ void round_x(const float* __restrict__ x, __half* __restrict__ xr, int n4) {
    int idx = blockIdx.x * blockDim.x + threadIdx.x;
    if (idx >= n4) return;
    float4 v = *(const float4*)(x + (size_t)idx * 4);
    __half2* dst = (__half2*)(xr + (size_t)idx * 4);
    dst[0] = __floats2half2_rn(v.x, v.y);
    dst[1] = __floats2half2_rn(v.z, v.w);
}

// ---------------- fp16 GEMM tile: 3-stage cp.async + ldmatrix + m16n8k16 -----
// C[bm:bm+128, bn:bn+128] = A(M x 512) @ W(rows x 512)^T, fp16 out, opt bias
__device__ __forceinline__ void gemm_tile(const __half* __restrict__ A,
                                          const __half* __restrict__ W,
                                          __half* __restrict__ C,
                                          int M, int ldC,
                                          const float* __restrict__ bias,
                                          int bm, int bn, __half* smem) {
    const int tid = threadIdx.x;
    const int lane = tid & 31;
    const int wid = tid >> 5;
    const int wm = (wid >> 2) << 6;   // 0 / 64
    const int wn = (wid & 3) << 5;    // 0 / 32 / 64 / 96
    const int g = lane >> 2;
    const int tig = lane & 3;

    const unsigned int smem_u = (unsigned int)__cvta_generic_to_shared(smem);

    // ldmatrix lane bases (bytes within slab, without ks term)
    int a_base[4];
#pragma unroll
    for (int mt = 0; mt < 4; mt++)
        a_base[mt] = (wm + mt * 16 + (lane & 15)) * 80 + ((lane >> 4) & 1) * 16;
    int b_base[2];
#pragma unroll
    for (int ntp = 0; ntp < 2; ntp++)
        b_base[ntp] = (wn + ntp * 16 + ((lane >> 4) << 3) + (lane & 7)) * 80 +
                      ((lane >> 3) & 1) * 16;

    float acc[4][4][4];
#pragma unroll
    for (int mt = 0; mt < 4; mt++)
#pragma unroll
        for (int nt = 0; nt < 4; nt++)
#pragma unroll
            for (int r = 0; r < 4; r++) acc[mt][nt][r] = 0.f;

    auto issue = [&](int buf, int K0) {   // K0 in halfs
        unsigned int sb = smem_u + buf * 2 * SLABB;
#pragma unroll
        for (int i = 0; i < 2; i++) {
            int id = tid + i * 256;
            int row = id & 127;
            int q = id >> 7;
            int gr = bm + row;
            int zf = (gr < M) ? 16 : 0;
            const __half* src = A + (size_t)(zf ? gr : 0) * DD + K0 + q * 8;
            asm volatile("cp.async.cg.shared.global [%0], [%1], 16, %2;"
                         :: "r"(sb + (unsigned)(row * 80 + q * 16)),
                            "l"(src), "r"(zf));
        }
        unsigned int sbw = sb + SLABB;
#pragma unroll
        for (int i = 0; i < 2; i++) {
            int id = tid + i * 256;
            int row = id & 127;
            int q = id >> 7;
            const __half* src = W + (size_t)(bn + row) * DD + K0 + q * 8;
            asm volatile("cp.async.cg.shared.global [%0], [%1], 16;"
                         :: "r"(sbw + (unsigned)(row * 80 + q * 16)),
                            "l"(src));
        }
        asm volatile("cp.async.commit_group;");
    };

    issue(0, 0);
    issue(1, 32);
    int bfill = 2, bread = 0;

    for (int s = 0; s < 16; s++) {
        if (s < 15) asm volatile("cp.async.wait_group 1;");
        else        asm volatile("cp.async.wait_group 0;");
        __syncthreads();
        if (s + 2 < 16) {
            issue(bfill, (s + 2) * 32);
            if (++bfill == 3) bfill = 0;
        }

        unsigned int As = smem_u + bread * 2 * SLABB;
        unsigned int Ws = As + SLABB;
        if (++bread == 3) bread = 0;

#pragma unroll
        for (int ks = 0; ks < 2; ks++) {
            const int kb = ks * 32;
            unsigned int a[4][4];
#pragma unroll
            for (int mt = 0; mt < 4; mt++) {
                asm volatile("ldmatrix.sync.aligned.m8n8.x4.shared.b16 "
                             "{%0,%1,%2,%3}, [%4];"
                             : "=r"(a[mt][0]), "=r"(a[mt][1]),
                               "=r"(a[mt][2]), "=r"(a[mt][3])
                             : "r"(As + (unsigned)(a_base[mt] + kb)));
            }
            unsigned int b[2][4];
#pragma unroll
            for (int ntp = 0; ntp < 2; ntp++) {
                asm volatile("ldmatrix.sync.aligned.m8n8.x4.shared.b16 "
                             "{%0,%1,%2,%3}, [%4];"
                             : "=r"(b[ntp][0]), "=r"(b[ntp][1]),
                               "=r"(b[ntp][2]), "=r"(b[ntp][3])
                             : "r"(Ws + (unsigned)(b_base[ntp] + kb)));
            }
#pragma unroll
            for (int mt = 0; mt < 4; mt++)
#pragma unroll
                for (int nt = 0; nt < 4; nt++) {
                    float* c = acc[mt][nt];
                    unsigned int b0 = b[nt >> 1][(nt & 1) * 2];
                    unsigned int b1 = b[nt >> 1][(nt & 1) * 2 + 1];
                    asm volatile(
                        "mma.sync.aligned.m16n8k16.row.col.f32.f16.f16.f32 "
                        "{%0,%1,%2,%3}, {%4,%5,%6,%7}, {%8,%9}, {%0,%1,%2,%3};"
                        : "+f"(c[0]), "+f"(c[1]), "+f"(c[2]), "+f"(c[3])
                        : "r"(a[mt][0]), "r"(a[mt][1]), "r"(a[mt][2]), "r"(a[mt][3]),
                          "r"(b0), "r"(b1));
                }
        }
    }
    __syncthreads();   // protect smem before next tile / reuse

#pragma unroll
    for (int mt = 0; mt < 4; mt++) {
        int row0 = bm + wm + (mt << 4) + g;
#pragma unroll
        for (int nt = 0; nt < 4; nt++) {
            int col = bn + wn + (nt << 3) + (tig << 1);
            float b0 = 0.f, b1 = 0.f;
            if (bias) { b0 = bias[col]; b1 = bias[col + 1]; }
            if (row0 < M) {
                *(__half2*)(C + (size_t)row0 * ldC + col) =
                    __floats2half2_rn(acc[mt][nt][0] + b0, acc[mt][nt][1] + b1);
            }
            if (row0 + 8 < M) {
                *(__half2*)(C + (size_t)(row0 + 8) * ldC + col) =
                    __floats2half2_rn(acc[mt][nt][2] + b0, acc[mt][nt][3] + b1);
            }
        }
    }
}

// ---------------- merged big-P GEMM: iou (all nodes) + f (internal) ----------
#define TILES_P_IOU (12 * 256)
__global__ __launch_bounds__(256, 2) void big_P_gemm() {
    extern __shared__ __half smem[];
    int t = blockIdx.x;
    if (t < TILES_P_IOU) {
        int by = t / 12, bx = t % 12;
        gemm_tile(g_xr, g_Wx, g_P, N_NODES, G4, g_b, by * 128, bx * 128, smem);
    } else {
        int t2 = t - TILES_P_IOU;
        int by = t2 >> 2, bx = t2 & 3;
        gemm_tile(g_xr, g_Wx + (size_t)1536 * DD, g_P + 1536,
                  (1 << (DEPTH - 1)) - 1, G4, g_b + 1536, by * 128, bx * 128, smem);
    }
}

// ---------------- merged level GEMMs ----------------
__global__ __launch_bounds__(256, 2) void level_gemms(int cnt) {
    extern __shared__ __half smem[];
    int cs = 2 * cnt - 1;
    int tiles_i = (cnt >> 7) * 12;
    int t = blockIdx.x;
    if (t < tiles_i) {
        int by = t / 12, bx = t % 12;
        gemm_tile(g_hs, g_Wh, g_Giou, cnt, 1536, nullptr, by * 128, bx * 128, smem);
    } else {
        int t2 = t - tiles_i;
        int by = t2 >> 2, bx = t2 & 3;
        gemm_tile(g_h + (size_t)cs * HH, g_Wh + (size_t)(3 * HH) * DD,
                  g_Gf, 2 * cnt, 512, nullptr, by * 128, bx * 128, smem);
    }
}

// ---------------- combine unit (fused pair-sum) ----------------
__device__ __forceinline__ void combine_unit(int u, int U, int start, int cs,
                                             bool write_hs, float4* sh) {
    float4 hfull = make_float4(0.f, 0.f, 0.f, 0.f);
    int b = u >> 7, j4 = (u & 127) << 2;
    if (u < U) {
        size_t n = (size_t)(start + b);
        const __half* Pp = g_P + n * G4;
        const __half* Gi = g_Giou + (size_t)b * 1536;
        float4 pi = ldh4(Pp + j4);
        float4 po = ldh4(Pp + HH + j4);
        float4 pu = ldh4(Pp + 2 * HH + j4);
        float4 pf = ldh4(Pp + 3 * HH + j4);
        float4 gi = ldh4(Gi + j4);
        float4 go = ldh4(Gi + HH + j4);
        float4 gu = ldh4(Gi + 2 * HH + j4);
        float4 gfl = ldh4(g_Gf + (size_t)(2 * b) * HH + j4);
        float4 gfr = ldh4(g_Gf + (size_t)(2 * b + 1) * HH + j4);
        float4 cl = *(const float4*)(g_c + (size_t)(cs + 2 * b) * HH + j4);
        float4 cr = *(const float4*)(g_c + (size_t)(cs + 2 * b + 1) * HH + j4);
        float4 c4;
#define COMB(X)                                                  \
        {                                                        \
            float i_ = sig_fast(pi.X + gi.X);                    \
            float o_ = sig_fast(po.X + go.X);                    \
            float u_ = tanh_fast(pu.X + gu.X);                   \
            float fl_ = sig_fast(pf.X + gfl.X);                  \
            float fr_ = sig_fast(pf.X + gfr.X);                  \
            c4.X = i_ * u_ + fl_ * cl.X + fr_ * cr.X;            \
            hfull.X = o_ * tanh_fast(c4.X);                      \
        }
        COMB(x) COMB(y) COMB(z) COMB(w)
#undef COMB
        *(float4*)(g_c + n * HH + j4) = c4;
        __half2* hd = (__half2*)(g_h + n * HH + j4);
        hd[0] = __floats2half2_rn(hfull.x, hfull.y);
        hd[1] = __floats2half2_rn(hfull.z, hfull.w);
        if (n == 0) *(float4*)(g_h0 + j4) = hfull;
    }
    sh[threadIdx.x] = hfull;
    __syncthreads();
    if (write_hs && threadIdx.x < 128 && u < U) {
        float4 o = sh[threadIdx.x + 128];
        __half2* hd = (__half2*)(g_hs + (size_t)(b >> 1) * HH + j4);
        hd[0] = __floats2half2_rn(hfull.x + o.x, hfull.y + o.y);
        hd[1] = __floats2half2_rn(hfull.z + o.z, hfull.w + o.w);
    }
    __syncthreads();
}

// ---------------- big-level combine ----------------
__global__ void combine_big(int start, int cnt, int cs) {
    __shared__ float4 sh[256];
    int u = blockIdx.x * 256 + threadIdx.x;
    combine_unit(u, cnt << 7, start, cs, true, sh);
}

// ---------------- leaf level (+ fused pair-sum) ----------------
__global__ void leaf_kernel() {
    __shared__ float4 sh[256];
    int u = blockIdx.x * 256 + threadIdx.x;
    int b = u >> 7, j4 = (u & 127) << 2;
    size_t n = (size_t)((1 << (DEPTH - 1)) - 1 + b);
    const __half* Pp = g_P + n * G4;
    float4 pi = ldh4(Pp + j4);
    float4 po = ldh4(Pp + HH + j4);
    float4 pu = ldh4(Pp + 2 * HH + j4);
    float4 c4, hfull;
#define LEAF1(X)                                             \
    {                                                        \
        float i_ = sig_fast(pi.X), o_ = sig_fast(po.X);      \
        float u_ = tanh_fast(pu.X);                          \
        c4.X = i_ * u_;                                      \
        hfull.X = o_ * tanh_fast(c4.X);                      \
    }
    LEAF1(x) LEAF1(y) LEAF1(z) LEAF1(w)
#undef LEAF1
    *(float4*)(g_c + n * HH + j4) = c4;
    __half2* hd = (__half2*)(g_h + n * HH + j4);
    hd[0] = __floats2half2_rn(hfull.x, hfull.y);
    hd[1] = __floats2half2_rn(hfull.z, hfull.w);
    sh[threadIdx.x] = hfull;
    __syncthreads();
    if (threadIdx.x < 128) {
        float4 o = sh[threadIdx.x + 128];
        __half2* hs = (__half2*)(g_hs + (size_t)(b >> 1) * HH + j4);
        hs[0] = __floats2half2_rn(hfull.x + o.x, hfull.y + o.y);
        hs[1] = __floats2half2_rn(hfull.z + o.z, hfull.w + o.w);
    }
}

// ---------------- software grid barrier (replay-safe) ----------------
__device__ __forceinline__ void grid_sync(unsigned int gen, unsigned int rel_base) {
    __syncthreads();
    if (threadIdx.x == 0) {
        __threadfence();
        unsigned int a = atomicAdd(&g_bar_cnt, 1);
        if (a == NCTA_PERS - 1) {
            g_bar_cnt = 0;
            __threadfence();
            atomicAdd(&g_bar_rel, 1);
        } else {
            while (*(volatile unsigned int*)&g_bar_rel - rel_base < gen) { }
        }
        __threadfence();
    }
    __syncthreads();
}

// ---------------- persistent kernel: levels 9..0 ----------------
__global__ __launch_bounds__(256) void small_levels() {
    extern __shared__ __half smem[];
    unsigned int rel_base = *(volatile unsigned int*)&g_bar_rel;
    unsigned int gen = 0;
    for (int lvl = 9; lvl >= 0; lvl--) {
        int cnt = 1 << lvl;
        int start = cnt - 1;
        int cs = 2 * cnt - 1;
        int tiles_i = ((cnt + 127) >> 7) * 12;
        int tiles_f = ((2 * cnt + 127) >> 7) * 4;
        int tot = tiles_i + tiles_f;
        for (int t = blockIdx.x; t < tot; t += NCTA_PERS) {
            if (t < tiles_i) {
                int by = t / 12, bx = t % 12;
                gemm_tile(g_hs, g_Wh, g_Giou, cnt, 1536, nullptr,
                          by * 128, bx * 128, smem);
            } else {
                int t2 = t - tiles_i;
                int by = t2 >> 2, bx = t2 & 3;
                gemm_tile(g_h + (size_t)cs * HH, g_Wh + (size_t)(3 * HH) * DD,
                          g_Gf, 2 * cnt, 512, nullptr, by * 128, bx * 128, smem);
            }
        }
        gen++; grid_sync(gen, rel_base);
        int U = cnt << 7;
        for (int base = blockIdx.x * 256; base < U; base += NCTA_PERS * 256) {
            combine_unit(base + (int)threadIdx.x, U, start, cs, lvl > 0,
                         (float4*)smem);
        }
        gen++; grid_sync(gen, rel_base);
    }
}

// ---------------- output: [h[0] | c[0]] ----------------
__global__ void write_out(float* __restrict__ out, int out_size) {
    int j = blockIdx.x * blockDim.x + threadIdx.x;
    if (j < HH && j < out_size) out[j] = g_h0[j];
    int j2 = j + HH;
    if (j < HH && j2 < out_size) out[j2] = g_c[j];
}

extern "C" void kernel_launch(void* const* d_in, const int* in_sizes, int n_in,
                              void* d_out, int out_size) {
    const float* x  = (const float*)d_in[0];
    const float* Wi = (const float*)d_in[1];
    const float* bi = (const float*)d_in[2];
    const float* Wf = (const float*)d_in[3];
    const float* bf = (const float*)d_in[4];
    const float* Wo = (const float*)d_in[5];
    const float* bo = (const float*)d_in[6];
    const float* Wu = (const float*)d_in[7];
    const float* bu = (const float*)d_in[8];
    float* out = (float*)d_out;

    __half* pxr;
    cudaGetSymbolAddress((void**)&pxr, g_xr);

    const int SMEM_GEMM = 6 * SLABB;   // 61440 B (3 stages x 2 slabs)
    cudaFuncSetAttribute(big_P_gemm,
                         cudaFuncAttributeMaxDynamicSharedMemorySize, SMEM_GEMM);
    cudaFuncSetAttribute(level_gemms,
                         cudaFuncAttributeMaxDynamicSharedMemorySize, SMEM_GEMM);
    cudaFuncSetAttribute(small_levels,
                         cudaFuncAttributeMaxDynamicSharedMemorySize, SMEM_GEMM);

    pack_weights<<<(G4 * DD + 255) / 256, 256>>>(Wi, bi, Wf, bf, Wo, bo, Wu, bu);
    round_x<<<(N_NODES * (DD / 4) + 255) / 256, 256>>>(x, pxr, N_NODES * (DD / 4));

    // P: iou for all nodes + f for internal nodes, one launch
    {
        int grid = TILES_P_IOU + 4 * 128;
        big_P_gemm<<<grid, 256, SMEM_GEMM>>>();
    }

    // leaves (+ pair-sum for level 13)
    leaf_kernel<<<(1 << (DEPTH - 1)) * 128 / 256, 256>>>();

    // big internal levels 13..10
    for (int lvl = DEPTH - 2; lvl >= 10; lvl--) {
        int cnt = 1 << lvl;
        int start = cnt - 1;
        int cs = 2 * cnt - 1;
        int grid = (cnt >> 7) * 12 + ((2 * cnt) >> 7) * 4;
        level_gemms<<<grid, 256, SMEM_GEMM>>>(cnt);
        combine_big<<<cnt * 128 / 256, 256>>>(start, cnt, cs);
    }

    // small levels 9..0 in one persistent launch
    small_levels<<<NCTA_PERS, 256, SMEM_GEMM>>>();

    write_out<<<(2 * HH + 255) / 256, 256>>>(out, out_size);
}